// round 1
// baseline (speedup 1.0000x reference)
#include <cuda_runtime.h>

#define Bq  1024
#define Ssz 20000
#define Dsz 256
#define Hh  4
#define DhN 64
#define SW  625   // mask words per batch row (20000/32)
#define NCH 25    // S chunks (split-S)
#define WPC 25    // words per chunk (25*25 = 625)

// ---------------- scratch (static device globals; no allocation) ----------------
__device__ float    g_q[Bq * Dsz];                         // 1 MB
__device__ float    g_kv[(size_t)Ssz * 512];               // 41 MB  [s][0:256]=k, [256:512]=v
__device__ unsigned g_maskT[SW * Bq];                      // 2.5 MB, word-major: [w][b]
__device__ float    g_part[(size_t)NCH * Bq * Hh * DhN];   // 26 MB  unnormalized ctx partials
__device__ float    g_partl[NCH * Bq * Hh];                // softmax-denominator partials
__device__ float    g_vpart[100 * Dsz];
__device__ float    g_vmean[Dsz];
__device__ float    g_ctx[Bq * Dsz];

// ---------------- mask bit-packing (transposed: coalesced loads in attention) ---
__global__ void pack_mask_kernel(const int* __restrict__ act) {
    int b = blockIdx.x;
    int warp = threadIdx.x >> 5, lane = threadIdx.x & 31;
    for (int w = warp; w < SW; w += 8) {
        int s = w * 32 + lane;
        unsigned m = __ballot_sync(0xFFFFFFFFu, act[(size_t)b * Ssz + s] > 0);
        if (lane == 0) g_maskT[w * Bq + b] = m;
    }
}

// ---------------- C[M][N] = A[M][256] @ Bw[N][256]^T + bias[N] -------------------
// BM=BN=64, BK=16, 256 threads, 4x4 micro-tiles.
__global__ __launch_bounds__(256) void gemm_abt(const float* __restrict__ A,
                                                const float* __restrict__ Bw,
                                                const float* __restrict__ bias,
                                                float* __restrict__ C,
                                                int M, int N) {
    __shared__ float As[16][68];   // [k][m]
    __shared__ float Bs[16][68];   // [k][n]
    int t  = threadIdx.x;
    int m0 = blockIdx.y * 64, n0 = blockIdx.x * 64;
    int lr = t >> 2, lc = (t & 3) * 4;
    int ty = t >> 4, tx = t & 15;
    float acc[4][4] = {};
    for (int k0 = 0; k0 < 256; k0 += 16) {
        float4 av = make_float4(0.f, 0.f, 0.f, 0.f);
        if (m0 + lr < M)
            av = *(const float4*)(A + (size_t)(m0 + lr) * 256 + k0 + lc);
        As[lc + 0][lr] = av.x; As[lc + 1][lr] = av.y;
        As[lc + 2][lr] = av.z; As[lc + 3][lr] = av.w;
        float4 bv = *(const float4*)(Bw + (size_t)(n0 + lr) * 256 + k0 + lc);
        Bs[lc + 0][lr] = bv.x; Bs[lc + 1][lr] = bv.y;
        Bs[lc + 2][lr] = bv.z; Bs[lc + 3][lr] = bv.w;
        __syncthreads();
#pragma unroll
        for (int k = 0; k < 16; k++) {
            float4 a = *(const float4*)&As[k][ty * 4];
            float4 b = *(const float4*)&Bs[k][tx * 4];
            acc[0][0] += a.x * b.x; acc[0][1] += a.x * b.y; acc[0][2] += a.x * b.z; acc[0][3] += a.x * b.w;
            acc[1][0] += a.y * b.x; acc[1][1] += a.y * b.y; acc[1][2] += a.y * b.z; acc[1][3] += a.y * b.w;
            acc[2][0] += a.z * b.x; acc[2][1] += a.z * b.y; acc[2][2] += a.z * b.z; acc[2][3] += a.z * b.w;
            acc[3][0] += a.w * b.x; acc[3][1] += a.w * b.y; acc[3][2] += a.w * b.z; acc[3][3] += a.w * b.w;
        }
        __syncthreads();
    }
    float4 bb = *(const float4*)(bias + n0 + tx * 4);
#pragma unroll
    for (int i = 0; i < 4; i++) {
        int m = m0 + ty * 4 + i;
        if (m < M) {
            float4 o = make_float4(acc[i][0] + bb.x, acc[i][1] + bb.y,
                                   acc[i][2] + bb.z, acc[i][3] + bb.w);
            *(float4*)(C + (size_t)m * N + n0 + tx * 4) = o;
        }
    }
}

// ---------------- v_mean = column mean of V (2-stage, deterministic) -------------
__global__ void vmean1_kernel() {
    int c = blockIdx.x, d = threadIdx.x;
    float s = 0.f;
    for (int i = 0; i < 200; i++)
        s += g_kv[(size_t)(c * 200 + i) * 512 + 256 + d];
    g_vpart[c * Dsz + d] = s;
}
__global__ void vmean2_kernel() {
    int d = threadIdx.x;
    float s = 0.f;
    for (int c = 0; c < 100; c++) s += g_vpart[c * Dsz + d];
    g_vmean[d] = s * (1.0f / (float)Ssz);
}

// ---------------- split-S attention ---------------------------------------------
// grid: (NCH chunks, 16 batch tiles of 64, 4 heads), 256 threads.
// Unnormalized exp (scores ~ N(0,1): safe in fp32), masked entries contribute 0.
__global__ __launch_bounds__(256) void attn_kernel() {
    const int sc = blockIdx.x;
    const int bt = blockIdx.y;
    const int h  = blockIdx.z;
    __shared__ float qs[64][65];   // [b][k]
    __shared__ float kst[64][36];  // [k][s]  (transposed)
    __shared__ float vs[32][68];   // [s][d]
    __shared__ float ps[64][36];   // [b][s]  scores -> probs
    const int t = threadIdx.x;

    { // load Q tile (64 b x 64 k)
        int r = t >> 2, c0 = (t & 3) * 16;
        const float* src = g_q + (size_t)(bt * 64 + r) * Dsz + h * 64 + c0;
#pragma unroll
        for (int u = 0; u < 4; u++) {
            float4 v = *(const float4*)(src + u * 4);
            qs[r][c0 + u * 4 + 0] = v.x;
            qs[r][c0 + u * 4 + 1] = v.y;
            qs[r][c0 + u * 4 + 2] = v.z;
            qs[r][c0 + u * 4 + 3] = v.w;
        }
    }
    float ctx[4][4] = {};
    float lacc = 0.f;
    const int kr = t >> 3,        kc = (t & 7) * 8;   // K/V load map
    const int sm = (t >> 3) * 2,  sn = (t & 7) * 4;   // scores map (2b x 4s)
    const int cm = (t >> 4) * 4,  cn = (t & 15) * 4;  // ctx map (4b x 4d)
    __syncthreads();

    for (int wi = 0; wi < WPC; wi++) {
        const int w  = sc * WPC + wi;
        const int s0 = w * 32;
        { // load K subtile transposed + V subtile (32 s rows)
            const float* kp = g_kv + (size_t)(s0 + kr) * 512 + h * 64 + kc;
            float4 k0 = *(const float4*)kp;
            float4 k1 = *(const float4*)(kp + 4);
            kst[kc + 0][kr] = k0.x; kst[kc + 1][kr] = k0.y;
            kst[kc + 2][kr] = k0.z; kst[kc + 3][kr] = k0.w;
            kst[kc + 4][kr] = k1.x; kst[kc + 5][kr] = k1.y;
            kst[kc + 6][kr] = k1.z; kst[kc + 7][kr] = k1.w;
            const float* vp = kp + 256;
            *(float4*)&vs[kr][kc]     = *(const float4*)vp;
            *(float4*)&vs[kr][kc + 4] = *(const float4*)(vp + 4);
        }
        __syncthreads();
        { // scores = Q @ K^T / 8
            float s00=0,s01=0,s02=0,s03=0,s10=0,s11=0,s12=0,s13=0;
#pragma unroll 16
            for (int k = 0; k < 64; k++) {
                float4 bb = *(const float4*)&kst[k][sn];
                float a0 = qs[sm][k], a1 = qs[sm + 1][k];
                s00 += a0*bb.x; s01 += a0*bb.y; s02 += a0*bb.z; s03 += a0*bb.w;
                s10 += a1*bb.x; s11 += a1*bb.y; s12 += a1*bb.z; s13 += a1*bb.w;
            }
            const float f = 0.125f;
            *(float4*)&ps[sm][sn]     = make_float4(s00*f, s01*f, s02*f, s03*f);
            *(float4*)&ps[sm + 1][sn] = make_float4(s10*f, s11*f, s12*f, s13*f);
        }
        __syncthreads();
        if (t < 64) { // mask + exp, one row per thread
            unsigned mw = g_maskT[w * Bq + bt * 64 + t];
            float ls = 0.f;
#pragma unroll 8
            for (int j = 0; j < 32; j++) {
                float v = 0.f;
                if ((mw >> j) & 1u) v = __expf(ps[t][j]);
                ps[t][j] = v;
                ls += v;
            }
            lacc += ls;
        }
        __syncthreads();
        { // ctx += P @ V
#pragma unroll 16
            for (int s = 0; s < 32; s++) {
                float4 bv = *(const float4*)&vs[s][cn];
                float a0 = ps[cm][s], a1 = ps[cm+1][s], a2 = ps[cm+2][s], a3 = ps[cm+3][s];
                ctx[0][0]+=a0*bv.x; ctx[0][1]+=a0*bv.y; ctx[0][2]+=a0*bv.z; ctx[0][3]+=a0*bv.w;
                ctx[1][0]+=a1*bv.x; ctx[1][1]+=a1*bv.y; ctx[1][2]+=a1*bv.z; ctx[1][3]+=a1*bv.w;
                ctx[2][0]+=a2*bv.x; ctx[2][1]+=a2*bv.y; ctx[2][2]+=a2*bv.z; ctx[2][3]+=a2*bv.w;
                ctx[3][0]+=a3*bv.x; ctx[3][1]+=a3*bv.y; ctx[3][2]+=a3*bv.z; ctx[3][3]+=a3*bv.w;
            }
        }
        __syncthreads();
    }
#pragma unroll
    for (int i = 0; i < 4; i++) {
        size_t idx = (((size_t)sc * Bq + bt * 64 + cm + i) * Hh + h) * DhN + cn;
        *(float4*)&g_part[idx] = make_float4(ctx[i][0], ctx[i][1], ctx[i][2], ctx[i][3]);
    }
    if (t < 64)
        g_partl[((size_t)sc * Bq + bt * 64 + t) * Hh + h] = lacc;
}

// ---------------- merge partials, normalize, inactive-row fallback ---------------
__global__ void reduce_ctx_kernel() {
    int b = blockIdx.x, d = threadIdx.x;
    int h = d >> 6, dd = d & 63;
    float l = 0.f, s = 0.f;
    for (int c = 0; c < NCH; c++) {
        l += g_partl[((size_t)c * Bq + b) * Hh + h];
        s += g_part[(((size_t)c * Bq + b) * Hh + h) * DhN + dd];
    }
    g_ctx[b * Dsz + d] = (l > 0.f) ? (s / l) : g_vmean[d];
}

// ---------------- launch ---------------------------------------------------------
extern "C" void kernel_launch(void* const* d_in, const int* in_sizes, int n_in,
                              void* d_out, int out_size) {
    const int*   act   = (const int*)d_in[0];
    const float* nc    = (const float*)d_in[1];
    const float* emb   = (const float*)d_in[2];
    const float* w_in  = (const float*)d_in[3];
    const float* b_in  = (const float*)d_in[4];
    const float* w_out = (const float*)d_in[5];
    const float* b_out = (const float*)d_in[6];
    float* out = (float*)d_out;
    (void)in_sizes; (void)n_in; (void)out_size;

    void *p_kv = 0, *p_q = 0, *p_ctx = 0;
    cudaGetSymbolAddress(&p_kv, g_kv);
    cudaGetSymbolAddress(&p_q, g_q);
    cudaGetSymbolAddress(&p_ctx, g_ctx);

    pack_mask_kernel<<<Bq, 256>>>(act);
    // K,V projection: rows 256..767 of in_proj_w  ->  g_kv[s][0:256]=k, [256:512]=v
    gemm_abt<<<dim3(8, 313), 256>>>(emb, w_in + 256 * 256, b_in + 256, (float*)p_kv, Ssz, 512);
    // Q projection: rows 0..255
    gemm_abt<<<dim3(4, 16), 256>>>(nc, w_in, b_in, (float*)p_q, Bq, 256);
    vmean1_kernel<<<100, 256>>>();
    vmean2_kernel<<<1, 256>>>();
    attn_kernel<<<dim3(NCH, Bq / 64, Hh), 256>>>();
    reduce_ctx_kernel<<<Bq, 256>>>();
    // out projection
    gemm_abt<<<dim3(4, 16), 256>>>((const float*)p_ctx, w_out, b_out, out, Bq, 256);
}

// round 2
// speedup vs baseline: 2.0606x; 2.0606x over previous
#include <cuda_runtime.h>
#include <cstdint>

#define Bq   1024
#define Ssz  20000
#define Spad 20032          // 64 * 313
#define Dsz  256
#define Hh   4
#define SW2  626            // mask words per batch row incl. padded word
#define NCH  24             // split-S chunks
#define TTOT 313            // 64-row s-tiles total

// ---------------- scratch (static device globals; no allocation) ----------------
__device__ float    g_q[Bq * Dsz];                       // 1 MB
__device__ float    g_kv[(size_t)Spad * 512];            // 41 MB  [s][0:256]=k, [256:512]=v
__device__ unsigned g_maskT[SW2 * Bq];                   // 2.5 MB, word-major: [w][b]
__device__ float    g_part[(size_t)NCH * Bq * Dsz];      // 25 MB  [c][b][h*64+d]
__device__ float    g_partl[NCH * Bq * Hh];
__device__ float    g_vpart[400 * Dsz];
__device__ float    g_vmean[Dsz];
__device__ float    g_ctx[Bq * Dsz];

// ---------------- helpers --------------------------------------------------------
__device__ __forceinline__ float f2tf32(float x) {
    unsigned u;
    asm("cvt.rna.tf32.f32 %0, %1;" : "=r"(u) : "f"(x));
    return __uint_as_float(u);
}
__device__ __forceinline__ void mma_tf32(float* d,
        uint32_t a0, uint32_t a1, uint32_t a2, uint32_t a3,
        uint32_t b0, uint32_t b1) {
    asm volatile(
        "mma.sync.aligned.m16n8k8.row.col.f32.tf32.tf32.f32 "
        "{%0,%1,%2,%3},{%4,%5,%6,%7},{%8,%9},{%0,%1,%2,%3};"
        : "+f"(d[0]), "+f"(d[1]), "+f"(d[2]), "+f"(d[3])
        : "r"(a0), "r"(a1), "r"(a2), "r"(a3), "r"(b0), "r"(b1));
}

// ---------------- mask bit-packing (transposed; padded word zeroed) --------------
__global__ void pack_mask_kernel(const int* __restrict__ act) {
    int b = blockIdx.x;
    int warp = threadIdx.x >> 5, lane = threadIdx.x & 31;
    for (int w = warp; w < SW2; w += 8) {
        int s = w * 32 + lane;
        int a = (s < Ssz) ? act[(size_t)b * Ssz + s] : 0;
        unsigned m = __ballot_sync(0xFFFFFFFFu, a > 0);
        if (lane == 0) g_maskT[w * Bq + b] = m;
    }
}

// ---------------- SIMT GEMM (kept for the two tiny 1024x256 projections) ---------
__global__ __launch_bounds__(256) void gemm_abt(const float* __restrict__ A,
                                                const float* __restrict__ Bw,
                                                const float* __restrict__ bias,
                                                float* __restrict__ C,
                                                int M, int N) {
    __shared__ float As[16][68];
    __shared__ float Bs[16][68];
    int t  = threadIdx.x;
    int m0 = blockIdx.y * 64, n0 = blockIdx.x * 64;
    int lr = t >> 2, lc = (t & 3) * 4;
    int ty = t >> 4, tx = t & 15;
    float acc[4][4] = {};
    for (int k0 = 0; k0 < 256; k0 += 16) {
        float4 av = make_float4(0.f, 0.f, 0.f, 0.f);
        if (m0 + lr < M)
            av = *(const float4*)(A + (size_t)(m0 + lr) * 256 + k0 + lc);
        As[lc + 0][lr] = av.x; As[lc + 1][lr] = av.y;
        As[lc + 2][lr] = av.z; As[lc + 3][lr] = av.w;
        float4 bv = *(const float4*)(Bw + (size_t)(n0 + lr) * 256 + k0 + lc);
        Bs[lc + 0][lr] = bv.x; Bs[lc + 1][lr] = bv.y;
        Bs[lc + 2][lr] = bv.z; Bs[lc + 3][lr] = bv.w;
        __syncthreads();
#pragma unroll
        for (int k = 0; k < 16; k++) {
            float4 a = *(const float4*)&As[k][ty * 4];
            float4 b = *(const float4*)&Bs[k][tx * 4];
            acc[0][0] += a.x * b.x; acc[0][1] += a.x * b.y; acc[0][2] += a.x * b.z; acc[0][3] += a.x * b.w;
            acc[1][0] += a.y * b.x; acc[1][1] += a.y * b.y; acc[1][2] += a.y * b.z; acc[1][3] += a.y * b.w;
            acc[2][0] += a.z * b.x; acc[2][1] += a.z * b.y; acc[2][2] += a.z * b.z; acc[2][3] += a.z * b.w;
            acc[3][0] += a.w * b.x; acc[3][1] += a.w * b.y; acc[3][2] += a.w * b.z; acc[3][3] += a.w * b.w;
        }
        __syncthreads();
    }
    float4 bb = *(const float4*)(bias + n0 + tx * 4);
#pragma unroll
    for (int i = 0; i < 4; i++) {
        int m = m0 + ty * 4 + i;
        if (m < M) {
            float4 o = make_float4(acc[i][0] + bb.x, acc[i][1] + bb.y,
                                   acc[i][2] + bb.z, acc[i][3] + bb.w);
            *(float4*)(C + (size_t)m * N + n0 + tx * 4) = o;
        }
    }
}

// ---------------- KV projection: tf32 tensor-core GEMM ---------------------------
// C[20032 x 512] = A[s][256] @ Bw[n][256]^T + bias[n]; A zero-padded past 20000.
__global__ __launch_bounds__(256) void gemm_kv_tf32(const float* __restrict__ A,
                                                    const float* __restrict__ Bw,
                                                    const float* __restrict__ bias,
                                                    float* __restrict__ C,
                                                    int Mreal) {
    __shared__ float As[64][68];
    __shared__ float Bs[64][68];
    const int t = threadIdx.x;
    const int m0 = blockIdx.y * 64, n0 = blockIdx.x * 64;
    const int wi = t >> 5, lane = t & 31, g = lane >> 2, tg = lane & 3;
    const int mw_ = (wi >> 1) * 16, nw_ = (wi & 1) * 32;
    const int lr = t >> 2, lc0 = (t & 3) * 16;
    float acc[4][4] = {};
    for (int k0 = 0; k0 < 256; k0 += 64) {
#pragma unroll
        for (int u = 0; u < 4; u++) {
            int c = lc0 + u * 4;
            float4 av = make_float4(0.f, 0.f, 0.f, 0.f);
            if (m0 + lr < Mreal)
                av = *(const float4*)(A + (size_t)(m0 + lr) * 256 + k0 + c);
            As[lr][c + 0] = f2tf32(av.x); As[lr][c + 1] = f2tf32(av.y);
            As[lr][c + 2] = f2tf32(av.z); As[lr][c + 3] = f2tf32(av.w);
            float4 bv = *(const float4*)(Bw + (size_t)(n0 + lr) * 256 + k0 + c);
            Bs[lr][c + 0] = f2tf32(bv.x); Bs[lr][c + 1] = f2tf32(bv.y);
            Bs[lr][c + 2] = f2tf32(bv.z); Bs[lr][c + 3] = f2tf32(bv.w);
        }
        __syncthreads();
#pragma unroll
        for (int kk = 0; kk < 64; kk += 8) {
            uint32_t a0 = __float_as_uint(As[mw_ + g][kk + tg]);
            uint32_t a1 = __float_as_uint(As[mw_ + g + 8][kk + tg]);
            uint32_t a2 = __float_as_uint(As[mw_ + g][kk + tg + 4]);
            uint32_t a3 = __float_as_uint(As[mw_ + g + 8][kk + tg + 4]);
#pragma unroll
            for (int nt = 0; nt < 4; nt++) {
                uint32_t b0 = __float_as_uint(Bs[nw_ + nt * 8 + g][kk + tg]);
                uint32_t b1 = __float_as_uint(Bs[nw_ + nt * 8 + g][kk + tg + 4]);
                mma_tf32(acc[nt], a0, a1, a2, a3, b0, b1);
            }
        }
        __syncthreads();
    }
    const int r0 = m0 + mw_ + g, r1 = r0 + 8;
#pragma unroll
    for (int nt = 0; nt < 4; nt++) {
        int col = n0 + nw_ + nt * 8 + tg * 2;
        float bx = bias[col], by = bias[col + 1];
        *(float2*)(C + (size_t)r0 * 512 + col) = make_float2(acc[nt][0] + bx, acc[nt][1] + by);
        *(float2*)(C + (size_t)r1 * 512 + col) = make_float2(acc[nt][2] + bx, acc[nt][3] + by);
    }
}

// ---------------- v_mean = column mean of V (2-stage, deterministic) -------------
__global__ void vmean1_kernel() {
    int c = blockIdx.x, d = threadIdx.x;
    float s = 0.f;
    for (int i = 0; i < 50; i++)
        s += g_kv[(size_t)(c * 50 + i) * 512 + 256 + d];
    g_vpart[c * Dsz + d] = s;
}
__global__ void vmean2_kernel() {
    int d = threadIdx.x;
    float s = 0.f;
    for (int c = 0; c < 400; c++) s += g_vpart[c * Dsz + d];
    g_vmean[d] = s * (1.0f / (float)Ssz);
}

// ---------------- split-S attention, tf32 tensor cores ---------------------------
struct SmemAttn {
    float    qs[64][68];   // Q tile (pre-scaled by 1/8, tf32-rounded)
    float    ks[64][68];   // K subtile [s][d]
    float    vs[64][72];   // V subtile [s][d]
    float    ps[64][68];   // probs (tf32-rounded)
    unsigned mw[2][64];    // mask words for this s-tile
    float    lsum[2][64];  // per-n-half row sums
};

__global__ __launch_bounds__(256, 2) void attn_tf32() {
    extern __shared__ char smraw[];
    SmemAttn& S = *reinterpret_cast<SmemAttn*>(smraw);
    const int c  = blockIdx.x;
    const int bt = blockIdx.y;
    const int h  = blockIdx.z;
    const int t = threadIdx.x;
    const int wi = t >> 5, lane = t & 31, g = lane >> 2, tg = lane & 3;
    const int m0 = (wi >> 1) * 16;     // warp's 16 batch rows
    const int nb = (wi & 1) * 32;      // warp's 32-col half

    { // load Q tile, fold 1/sqrt(Dh)=1/8, round to tf32
        int r = t >> 2, c0 = (t & 3) * 16;
        const float* src = g_q + (size_t)(bt * 64 + r) * Dsz + h * 64 + c0;
#pragma unroll
        for (int u = 0; u < 4; u++) {
            float4 v = *(const float4*)(src + u * 4);
            S.qs[r][c0 + u * 4 + 0] = f2tf32(v.x * 0.125f);
            S.qs[r][c0 + u * 4 + 1] = f2tf32(v.y * 0.125f);
            S.qs[r][c0 + u * 4 + 2] = f2tf32(v.z * 0.125f);
            S.qs[r][c0 + u * 4 + 3] = f2tf32(v.w * 0.125f);
        }
    }
    float ctx[4][4] = {};
    float l0 = 0.f, l1 = 0.f;
    const int t0 = (TTOT * c) / NCH, t1 = (TTOT * (c + 1)) / NCH;
    __syncthreads();

    for (int ts = t0; ts < t1; ts++) {
        const int s0 = ts * 64;
        { // load K/V subtiles (tf32-rounded) + mask words
            int r = t >> 2, c0 = (t & 3) * 16;
            const float* kp = g_kv + (size_t)(s0 + r) * 512 + h * 64 + c0;
#pragma unroll
            for (int u = 0; u < 4; u++) {
                float4 k4 = *(const float4*)(kp + u * 4);
                S.ks[r][c0 + u * 4 + 0] = f2tf32(k4.x);
                S.ks[r][c0 + u * 4 + 1] = f2tf32(k4.y);
                S.ks[r][c0 + u * 4 + 2] = f2tf32(k4.z);
                S.ks[r][c0 + u * 4 + 3] = f2tf32(k4.w);
                float4 v4 = *(const float4*)(kp + 256 + u * 4);
                S.vs[r][c0 + u * 4 + 0] = f2tf32(v4.x);
                S.vs[r][c0 + u * 4 + 1] = f2tf32(v4.y);
                S.vs[r][c0 + u * 4 + 2] = f2tf32(v4.z);
                S.vs[r][c0 + u * 4 + 3] = f2tf32(v4.w);
            }
            if (t < 128)
                S.mw[t >> 6][t & 63] = g_maskT[(2 * ts + (t >> 6)) * Bq + bt * 64 + (t & 63)];
        }
        __syncthreads();
        // ---- scores = (Q/8) @ K^T (tensor cores) ----
        float sc[4][4] = {};
#pragma unroll
        for (int kk = 0; kk < 64; kk += 8) {
            uint32_t a0 = __float_as_uint(S.qs[m0 + g][kk + tg]);
            uint32_t a1 = __float_as_uint(S.qs[m0 + g + 8][kk + tg]);
            uint32_t a2 = __float_as_uint(S.qs[m0 + g][kk + tg + 4]);
            uint32_t a3 = __float_as_uint(S.qs[m0 + g + 8][kk + tg + 4]);
#pragma unroll
            for (int nt = 0; nt < 4; nt++) {
                uint32_t b0 = __float_as_uint(S.ks[nb + nt * 8 + g][kk + tg]);
                uint32_t b1 = __float_as_uint(S.ks[nb + nt * 8 + g][kk + tg + 4]);
                mma_tf32(sc[nt], a0, a1, a2, a3, b0, b1);
            }
        }
        // ---- mask + exp -> ps (tf32), accumulate row sums ----
        {
            const int r0 = m0 + g, r1 = m0 + g + 8;
            unsigned w0r0 = S.mw[0][r0], w1r0 = S.mw[1][r0];
            unsigned w0r1 = S.mw[0][r1], w1r1 = S.mw[1][r1];
#pragma unroll
            for (int nt = 0; nt < 4; nt++) {
                int cs = nb + nt * 8 + tg * 2;
                unsigned wr0 = (cs < 32) ? w0r0 : w1r0;
                unsigned wr1 = (cs < 32) ? w0r1 : w1r1;
                int bpos = cs & 31;
                float p00 = ((wr0 >> bpos) & 1u)       ? f2tf32(__expf(sc[nt][0])) : 0.f;
                float p01 = ((wr0 >> (bpos + 1)) & 1u) ? f2tf32(__expf(sc[nt][1])) : 0.f;
                float p10 = ((wr1 >> bpos) & 1u)       ? f2tf32(__expf(sc[nt][2])) : 0.f;
                float p11 = ((wr1 >> (bpos + 1)) & 1u) ? f2tf32(__expf(sc[nt][3])) : 0.f;
                l0 += p00 + p01;
                l1 += p10 + p11;
                *(float2*)&S.ps[r0][cs] = make_float2(p00, p01);
                *(float2*)&S.ps[r1][cs] = make_float2(p10, p11);
            }
        }
        __syncthreads();
        // ---- ctx += P @ V (tensor cores) ----
#pragma unroll
        for (int kk = 0; kk < 64; kk += 8) {
            uint32_t a0 = __float_as_uint(S.ps[m0 + g][kk + tg]);
            uint32_t a1 = __float_as_uint(S.ps[m0 + g + 8][kk + tg]);
            uint32_t a2 = __float_as_uint(S.ps[m0 + g][kk + tg + 4]);
            uint32_t a3 = __float_as_uint(S.ps[m0 + g + 8][kk + tg + 4]);
#pragma unroll
            for (int nt = 0; nt < 4; nt++) {
                uint32_t b0 = __float_as_uint(S.vs[kk + tg][nb + nt * 8 + g]);
                uint32_t b1 = __float_as_uint(S.vs[kk + tg + 4][nb + nt * 8 + g]);
                mma_tf32(ctx[nt], a0, a1, a2, a3, b0, b1);
            }
        }
        __syncthreads();
    }
    // ---- write partials ----
    {
        const int r0 = m0 + g, r1 = m0 + g + 8;
#pragma unroll
        for (int nt = 0; nt < 4; nt++) {
            int d = nb + nt * 8 + tg * 2;
            size_t base = ((size_t)c * Bq + bt * 64) * Dsz + (size_t)h * 64 + d;
            *(float2*)&g_part[base + (size_t)r0 * Dsz] = make_float2(ctx[nt][0], ctx[nt][1]);
            *(float2*)&g_part[base + (size_t)r1 * Dsz] = make_float2(ctx[nt][2], ctx[nt][3]);
        }
        l0 += __shfl_xor_sync(0xFFFFFFFFu, l0, 1);
        l0 += __shfl_xor_sync(0xFFFFFFFFu, l0, 2);
        l1 += __shfl_xor_sync(0xFFFFFFFFu, l1, 1);
        l1 += __shfl_xor_sync(0xFFFFFFFFu, l1, 2);
        if (tg == 0) {
            S.lsum[wi & 1][m0 + g]     = l0;
            S.lsum[wi & 1][m0 + g + 8] = l1;
        }
        __syncthreads();
        if (t < 64)
            g_partl[((size_t)c * Bq + bt * 64 + t) * Hh + h] = S.lsum[0][t] + S.lsum[1][t];
    }
}

// ---------------- merge partials, normalize, inactive-row fallback ---------------
__global__ void reduce_ctx_kernel() {
    int b = blockIdx.x, d = threadIdx.x;
    int h = d >> 6;
    float l = 0.f, s = 0.f;
    for (int c = 0; c < NCH; c++) {
        l += g_partl[((size_t)c * Bq + b) * Hh + h];
        s += g_part[((size_t)c * Bq + b) * Dsz + d];
    }
    g_ctx[b * Dsz + d] = (l > 0.f) ? (s / l) : g_vmean[d];
}

// ---------------- launch ---------------------------------------------------------
extern "C" void kernel_launch(void* const* d_in, const int* in_sizes, int n_in,
                              void* d_out, int out_size) {
    const int*   act   = (const int*)d_in[0];
    const float* nc    = (const float*)d_in[1];
    const float* emb   = (const float*)d_in[2];
    const float* w_in  = (const float*)d_in[3];
    const float* b_in  = (const float*)d_in[4];
    const float* w_out = (const float*)d_in[5];
    const float* b_out = (const float*)d_in[6];
    float* out = (float*)d_out;
    (void)in_sizes; (void)n_in; (void)out_size;

    void *p_kv = 0, *p_q = 0, *p_ctx = 0;
    cudaGetSymbolAddress(&p_kv, g_kv);
    cudaGetSymbolAddress(&p_q, g_q);
    cudaGetSymbolAddress(&p_ctx, g_ctx);

    cudaFuncSetAttribute(attn_tf32, cudaFuncAttributeMaxDynamicSharedMemorySize,
                         (int)sizeof(SmemAttn));

    pack_mask_kernel<<<Bq, 256>>>(act);
    // K,V projection (rows 256..767 of in_proj_w) -> g_kv, tensor cores
    gemm_kv_tf32<<<dim3(8, Spad / 64), 256>>>(emb, w_in + 256 * 256, b_in + 256,
                                              (float*)p_kv, Ssz);
    // Q projection (rows 0..255), SIMT (tiny)
    gemm_abt<<<dim3(4, 16), 256>>>(nc, w_in, b_in, (float*)p_q, Bq, 256);
    vmean1_kernel<<<400, 256>>>();
    vmean2_kernel<<<1, 256>>>();
    attn_tf32<<<dim3(NCH, Bq / 64, Hh), 256, sizeof(SmemAttn)>>>();
    reduce_ctx_kernel<<<Bq, 256>>>();
    // out projection, SIMT (tiny)
    gemm_abt<<<dim3(4, 16), 256>>>((const float*)p_ctx, w_out, b_out, out, Bq, 256);
}

// round 4
// speedup vs baseline: 3.6514x; 1.7720x over previous
#include <cuda_runtime.h>
#include <cuda_fp16.h>
#include <cstdint>

#define Bq   1024
#define Ssz  20000
#define Spad 20032          // 64 * 313
#define Dsz  256
#define Hh   4
#define SW2  626            // mask words per batch row incl. padded word
#define NCH  7              // split-S chunks (448 CTAs = one wave at 3/SM)
#define TTOT 313            // 64-row s-tiles total

// ---------------- scratch (static device globals; no allocation) ----------------
__device__ float    g_q[Bq * Dsz];
__device__ __half   g_kv[(size_t)Spad * 512];            // [s][0:256]=k, [256:512]=v (fp16)
__device__ unsigned g_maskT[SW2 * Bq];                   // word-major: [w][b]
__device__ float    g_part[(size_t)NCH * Bq * Dsz];      // [c][b][h*64+d]
__device__ float    g_partl[NCH * Bq * Hh];
__device__ float    g_vpart[400 * Dsz];
__device__ float    g_vmean[Dsz];
__device__ float    g_ctx[Bq * Dsz];

// ---------------- helpers --------------------------------------------------------
__device__ __forceinline__ uint32_t smem_u32(const void* p) {
    uint32_t a;
    asm("{ .reg .u64 t; cvta.to.shared.u64 t, %1; cvt.u32.u64 %0, t; }" : "=r"(a) : "l"(p));
    return a;
}
__device__ __forceinline__ uint32_t h2pack(float a, float b) {
    __half2 h = __floats2half2_rn(a, b);
    return *reinterpret_cast<uint32_t*>(&h);
}
// swizzled byte offset inside a 64-col (128B-row) half tile; ch = 8-half chunk
__device__ __forceinline__ int toff(int r, int ch) {
    return r * 128 + ((ch ^ (r & 7)) << 4);
}
__device__ __forceinline__ void ldsm_x4(uint32_t& r0, uint32_t& r1, uint32_t& r2,
                                        uint32_t& r3, uint32_t addr) {
    asm volatile("ldmatrix.sync.aligned.m8n8.x4.shared.b16 {%0,%1,%2,%3}, [%4];"
                 : "=r"(r0), "=r"(r1), "=r"(r2), "=r"(r3) : "r"(addr));
}
__device__ __forceinline__ void ldsm_x4_t(uint32_t& r0, uint32_t& r1, uint32_t& r2,
                                          uint32_t& r3, uint32_t addr) {
    asm volatile("ldmatrix.sync.aligned.m8n8.x4.trans.shared.b16 {%0,%1,%2,%3}, [%4];"
                 : "=r"(r0), "=r"(r1), "=r"(r2), "=r"(r3) : "r"(addr));
}
__device__ __forceinline__ void hmma(float* d, uint32_t a0, uint32_t a1, uint32_t a2,
                                     uint32_t a3, uint32_t b0, uint32_t b1) {
    asm volatile(
        "mma.sync.aligned.m16n8k16.row.col.f32.f16.f16.f32 "
        "{%0,%1,%2,%3},{%4,%5,%6,%7},{%8,%9},{%0,%1,%2,%3};"
        : "+f"(d[0]), "+f"(d[1]), "+f"(d[2]), "+f"(d[3])
        : "r"(a0), "r"(a1), "r"(a2), "r"(a3), "r"(b0), "r"(b1));
}

// ---------------- mask bit-packing (transposed; padded word zeroed) --------------
__global__ void pack_mask_kernel(const int* __restrict__ act) {
    int b = blockIdx.x;
    int warp = threadIdx.x >> 5, lane = threadIdx.x & 31;
    for (int w = warp; w < SW2; w += 8) {
        int s = w * 32 + lane;
        int a = (s < Ssz) ? act[(size_t)b * Ssz + s] : 0;
        unsigned m = __ballot_sync(0xFFFFFFFFu, a > 0);
        if (lane == 0) g_maskT[w * Bq + b] = m;
    }
}

// ---------------- SIMT GEMM (two tiny 1024x256 fp32 projections) -----------------
__global__ __launch_bounds__(256) void gemm_abt(const float* __restrict__ A,
                                                const float* __restrict__ Bw,
                                                const float* __restrict__ bias,
                                                float* __restrict__ C,
                                                int M, int N) {
    __shared__ float As[16][68];
    __shared__ float Bs[16][68];
    int t  = threadIdx.x;
    int m0 = blockIdx.y * 64, n0 = blockIdx.x * 64;
    int lr = t >> 2, lc = (t & 3) * 4;
    int ty = t >> 4, tx = t & 15;
    float acc[4][4] = {};
    for (int k0 = 0; k0 < 256; k0 += 16) {
        float4 av = make_float4(0.f, 0.f, 0.f, 0.f);
        if (m0 + lr < M)
            av = *(const float4*)(A + (size_t)(m0 + lr) * 256 + k0 + lc);
        As[lc + 0][lr] = av.x; As[lc + 1][lr] = av.y;
        As[lc + 2][lr] = av.z; As[lc + 3][lr] = av.w;
        float4 bv = *(const float4*)(Bw + (size_t)(n0 + lr) * 256 + k0 + lc);
        Bs[lc + 0][lr] = bv.x; Bs[lc + 1][lr] = bv.y;
        Bs[lc + 2][lr] = bv.z; Bs[lc + 3][lr] = bv.w;
        __syncthreads();
#pragma unroll
        for (int k = 0; k < 16; k++) {
            float4 a = *(const float4*)&As[k][ty * 4];
            float4 b = *(const float4*)&Bs[k][tx * 4];
            acc[0][0] += a.x * b.x; acc[0][1] += a.x * b.y; acc[0][2] += a.x * b.z; acc[0][3] += a.x * b.w;
            acc[1][0] += a.y * b.x; acc[1][1] += a.y * b.y; acc[1][2] += a.y * b.z; acc[1][3] += a.y * b.w;
            acc[2][0] += a.z * b.x; acc[2][1] += a.z * b.y; acc[2][2] += a.z * b.z; acc[2][3] += a.z * b.w;
            acc[3][0] += a.w * b.x; acc[3][1] += a.w * b.y; acc[3][2] += a.w * b.z; acc[3][3] += a.w * b.w;
        }
        __syncthreads();
    }
    float4 bb = *(const float4*)(bias + n0 + tx * 4);
#pragma unroll
    for (int i = 0; i < 4; i++) {
        int m = m0 + ty * 4 + i;
        if (m < M) {
            float4 o = make_float4(acc[i][0] + bb.x, acc[i][1] + bb.y,
                                   acc[i][2] + bb.z, acc[i][3] + bb.w);
            *(float4*)(C + (size_t)m * N + n0 + tx * 4) = o;
        }
    }
}

// ---------------- KV projection: fp16 mma.sync + ldmatrix ------------------------
// C[Spad x 512] (half) = A[s][256] @ Bw[n][256]^T + bias[n]
__global__ __launch_bounds__(256) void gemm_kv_h(const float* __restrict__ A,
                                                 const float* __restrict__ Bw,
                                                 const float* __restrict__ bias,
                                                 __half* __restrict__ C,
                                                 int Mreal) {
    __shared__ __align__(16) __half As[64 * 64];
    __shared__ __align__(16) __half Bs[64 * 64];
    char* ac = (char*)As; char* bc = (char*)Bs;
    const uint32_t ab = smem_u32(As), bb_ = smem_u32(Bs);
    const int t = threadIdx.x, w = t >> 5, lane = t & 31;
    const int m0 = blockIdx.y * 64, n0 = blockIdx.x * 64;
    const int mw_ = (w >> 1) * 16, nw_ = (w & 1) * 32;
    const int qr = lane >> 2, tg = lane & 3;
    const int aL4 = (lane >> 4) & 1, bL3 = (lane >> 3) & 1;
    const int ar = mw_ + (lane & 7) + (lane & 8), ar7 = ar & 7;
    const int br = nw_ + (lane & 7) + aL4 * 8, br7 = br & 7;
    float acc[4][4] = {};
    for (int k0 = 0; k0 < 256; k0 += 64) {
#pragma unroll
        for (int i = 0; i < 2; i++) {
            int idx = t + i * 256;
            int r = idx >> 3, ch = idx & 7;
            uint4 o = make_uint4(0u, 0u, 0u, 0u);
            if (m0 + r < Mreal) {
                const float* ap = A + (size_t)(m0 + r) * 256 + k0 + ch * 8;
                float4 x = *(const float4*)ap, y = *(const float4*)(ap + 4);
                o = make_uint4(h2pack(x.x, x.y), h2pack(x.z, x.w),
                               h2pack(y.x, y.y), h2pack(y.z, y.w));
            }
            *(uint4*)(ac + toff(r, ch)) = o;
            const float* bp = Bw + (size_t)(n0 + r) * 256 + k0 + ch * 8;
            float4 x = *(const float4*)bp, y = *(const float4*)(bp + 4);
            *(uint4*)(bc + toff(r, ch)) = make_uint4(h2pack(x.x, x.y), h2pack(x.z, x.w),
                                                     h2pack(y.x, y.y), h2pack(y.z, y.w));
        }
        __syncthreads();
#pragma unroll
        for (int kk = 0; kk < 64; kk += 16) {
            int c8 = kk >> 3;
            uint32_t a0, a1, a2, a3, b0, b1, b2, b3, c0, c1, c2, c3;
            ldsm_x4(a0, a1, a2, a3, ab + ar * 128 + (((c8 + aL4) ^ ar7) << 4));
            ldsm_x4(b0, b1, b2, b3, bb_ + br * 128 + (((c8 + bL3) ^ br7) << 4));
            hmma(acc[0], a0, a1, a2, a3, b0, b1);
            hmma(acc[1], a0, a1, a2, a3, b2, b3);
            ldsm_x4(c0, c1, c2, c3, bb_ + (br + 16) * 128 + (((c8 + bL3) ^ br7) << 4));
            hmma(acc[2], a0, a1, a2, a3, c0, c1);
            hmma(acc[3], a0, a1, a2, a3, c2, c3);
        }
        __syncthreads();
    }
    const int r0 = m0 + mw_ + qr, r1 = r0 + 8;
#pragma unroll
    for (int nt = 0; nt < 4; nt++) {
        int col = n0 + nw_ + nt * 8 + tg * 2;
        float bx = bias[col], by = bias[col + 1];
        *(__half2*)(C + (size_t)r0 * 512 + col) = __floats2half2_rn(acc[nt][0] + bx, acc[nt][1] + by);
        *(__half2*)(C + (size_t)r1 * 512 + col) = __floats2half2_rn(acc[nt][2] + bx, acc[nt][3] + by);
    }
}

// ---------------- v_mean (2-stage, deterministic, reads half V) ------------------
__global__ void vmean1_kernel() {
    int c = blockIdx.x, d = threadIdx.x;
    float s = 0.f;
    for (int i = 0; i < 50; i++)
        s += __half2float(g_kv[(size_t)(c * 50 + i) * 512 + 256 + d]);
    g_vpart[c * Dsz + d] = s;
}
__global__ void vmean2_kernel() {
    int d = threadIdx.x;
    float s = 0.f;
    for (int c = 0; c < 400; c++) s += g_vpart[c * Dsz + d];
    g_vmean[d] = s * (1.0f / (float)Ssz);
}

// ---------------- split-S attention: fp16 mma.sync + ldmatrix --------------------
// CTA: 64 batch x 64 d (one head); per 64-s tile: QK -> mask+exp -> PV.
__global__ __launch_bounds__(256, 3) void attn_h() {
    __shared__ __align__(16) __half qs[64 * 64];
    __shared__ __align__(16) __half ks[64 * 64];
    __shared__ __align__(16) __half vs[64 * 64];
    __shared__ __align__(16) __half ps[64 * 64];
    __shared__ unsigned mwsh[2][64];
    __shared__ float lsm[2][64];
    char* qc = (char*)qs; char* kc_ = (char*)ks; char* vc = (char*)vs; char* pc = (char*)ps;
    const uint32_t qb = smem_u32(qs), kb = smem_u32(ks), vb = smem_u32(vs), pb = smem_u32(ps);
    const int t = threadIdx.x, w = t >> 5, lane = t & 31;
    const int c = blockIdx.x, bt = blockIdx.y, h = blockIdx.z;
    const int mw_ = (w >> 1) * 16, nw_ = (w & 1) * 32;
    const int qr = lane >> 2, tg = lane & 3;
    const int aL4 = (lane >> 4) & 1, bL3 = (lane >> 3) & 1;
    const int ar = mw_ + (lane & 7) + (lane & 8), ar7 = ar & 7;
    const int br = nw_ + (lane & 7) + aL4 * 8, br7 = br & 7;
    const int vl7 = lane & 7;                  // PV B row low bits
    const int vc8 = (nw_ >> 3) + aL4;          // PV B col chunk (group 1)

    { // Q tile: fp32 -> half, scaled by 1/8
#pragma unroll
        for (int i = 0; i < 2; i++) {
            int idx = t + i * 256;
            int r = idx >> 3, ch = idx & 7;
            const float* qp = g_q + (size_t)(bt * 64 + r) * 256 + h * 64 + ch * 8;
            float4 x = *(const float4*)qp, y = *(const float4*)(qp + 4);
            *(uint4*)(qc + toff(r, ch)) =
                make_uint4(h2pack(x.x * 0.125f, x.y * 0.125f), h2pack(x.z * 0.125f, x.w * 0.125f),
                           h2pack(y.x * 0.125f, y.y * 0.125f), h2pack(y.z * 0.125f, y.w * 0.125f));
        }
    }
    float ctx[4][4] = {};
    float l0 = 0.f, l1 = 0.f;
    const int t0 = (TTOT * c) / NCH, t1 = (TTOT * (c + 1)) / NCH;
    const int r0 = mw_ + qr, r1 = r0 + 8;

    for (int ts = t0; ts < t1; ts++) {
        { // K,V half tiles: direct 16B copies; + mask words
#pragma unroll
            for (int i = 0; i < 2; i++) {
                int idx = t + i * 256;
                int r = idx >> 3, ch = idx & 7;
                const __half* kp = g_kv + (size_t)(ts * 64 + r) * 512 + h * 64 + ch * 8;
                *(uint4*)(kc_ + toff(r, ch)) = *(const uint4*)kp;
                *(uint4*)(vc + toff(r, ch)) = *(const uint4*)(kp + 256);
            }
            if (t < 128)
                mwsh[t >> 6][t & 63] = g_maskT[(size_t)(2 * ts + (t >> 6)) * Bq + bt * 64 + (t & 63)];
        }
        __syncthreads();
        // ---- scores = (Q/8) @ K^T ----
        float sc[4][4] = {};
#pragma unroll
        for (int kk = 0; kk < 64; kk += 16) {
            int c8 = kk >> 3;
            uint32_t a0, a1, a2, a3, b0, b1, b2, b3, c0, c1, c2, c3;
            ldsm_x4(a0, a1, a2, a3, qb + ar * 128 + (((c8 + aL4) ^ ar7) << 4));
            ldsm_x4(b0, b1, b2, b3, kb + br * 128 + (((c8 + bL3) ^ br7) << 4));
            hmma(sc[0], a0, a1, a2, a3, b0, b1);
            hmma(sc[1], a0, a1, a2, a3, b2, b3);
            ldsm_x4(c0, c1, c2, c3, kb + (br + 16) * 128 + (((c8 + bL3) ^ br7) << 4));
            hmma(sc[2], a0, a1, a2, a3, c0, c1);
            hmma(sc[3], a0, a1, a2, a3, c2, c3);
        }
        // ---- mask + exp -> ps (half), accumulate row sums ----
        {
            unsigned w0r0 = mwsh[0][r0], w1r0 = mwsh[1][r0];
            unsigned w0r1 = mwsh[0][r1], w1r1 = mwsh[1][r1];
#pragma unroll
            for (int nt = 0; nt < 4; nt++) {
                int cs = nw_ + nt * 8 + tg * 2;
                unsigned wr0 = (cs & 32) ? w1r0 : w0r0;
                unsigned wr1 = (cs & 32) ? w1r1 : w0r1;
                int bp = cs & 31;
                float p00 = ((wr0 >> bp) & 1u)       ? __half2float(__float2half_rn(__expf(sc[nt][0]))) : 0.f;
                float p01 = ((wr0 >> (bp + 1)) & 1u) ? __half2float(__float2half_rn(__expf(sc[nt][1]))) : 0.f;
                float p10 = ((wr1 >> bp) & 1u)       ? __half2float(__float2half_rn(__expf(sc[nt][2]))) : 0.f;
                float p11 = ((wr1 >> (bp + 1)) & 1u) ? __half2float(__float2half_rn(__expf(sc[nt][3]))) : 0.f;
                l0 += p00 + p01;
                l1 += p10 + p11;
                int chs = cs >> 3, lo = (cs & 7) * 2;
                *(uint32_t*)(pc + r0 * 128 + ((chs ^ (r0 & 7)) << 4) + lo) = h2pack(p00, p01);
                *(uint32_t*)(pc + r1 * 128 + ((chs ^ (r1 & 7)) << 4) + lo) = h2pack(p10, p11);
            }
        }
        __syncthreads();
        // ---- ctx += P @ V  (B via ldmatrix.trans on row-major V) ----
#pragma unroll
        for (int kk = 0; kk < 64; kk += 16) {
            int c8 = kk >> 3;
            int vr = kk + vl7 + bL3 * 8;
            uint32_t a0, a1, a2, a3, b0, b1, b2, b3, c0, c1, c2, c3;
            ldsm_x4(a0, a1, a2, a3, pb + ar * 128 + (((c8 + aL4) ^ ar7) << 4));
            ldsm_x4_t(b0, b1, b2, b3, vb + vr * 128 + ((vc8 ^ vl7) << 4));
            hmma(ctx[0], a0, a1, a2, a3, b0, b1);
            hmma(ctx[1], a0, a1, a2, a3, b2, b3);
            ldsm_x4_t(c0, c1, c2, c3, vb + vr * 128 + (((vc8 + 2) ^ vl7) << 4));
            hmma(ctx[2], a0, a1, a2, a3, c0, c1);
            hmma(ctx[3], a0, a1, a2, a3, c2, c3);
        }
        __syncthreads();
    }
    // ---- write partials ----
#pragma unroll
    for (int nt = 0; nt < 4; nt++) {
        int col = nw_ + nt * 8 + tg * 2;
        size_t base = ((size_t)c * Bq + bt * 64) * Dsz + (size_t)h * 64 + col;
        *(float2*)(g_part + base + (size_t)r0 * Dsz) = make_float2(ctx[nt][0], ctx[nt][1]);
        *(float2*)(g_part + base + (size_t)r1 * Dsz) = make_float2(ctx[nt][2], ctx[nt][3]);
    }
    l0 += __shfl_xor_sync(0xFFFFFFFFu, l0, 1);
    l0 += __shfl_xor_sync(0xFFFFFFFFu, l0, 2);
    l1 += __shfl_xor_sync(0xFFFFFFFFu, l1, 1);
    l1 += __shfl_xor_sync(0xFFFFFFFFu, l1, 2);
    if (tg == 0) {
        lsm[w & 1][r0] = l0;
        lsm[w & 1][r1] = l1;
    }
    __syncthreads();
    if (t < 64)
        g_partl[((size_t)c * Bq + bt * 64 + t) * Hh + h] = lsm[0][t] + lsm[1][t];
}

// ---------------- merge partials, normalize, inactive-row fallback ---------------
__global__ void reduce_ctx_kernel() {
    int b = blockIdx.x, d = threadIdx.x;
    int h = d >> 6;
    float l = 0.f, s = 0.f;
    for (int c = 0; c < NCH; c++) {
        l += g_partl[((size_t)c * Bq + b) * Hh + h];
        s += g_part[((size_t)c * Bq + b) * Dsz + d];
    }
    g_ctx[b * Dsz + d] = (l > 0.f) ? (s / l) : g_vmean[d];
}

// ---------------- launch ---------------------------------------------------------
extern "C" void kernel_launch(void* const* d_in, const int* in_sizes, int n_in,
                              void* d_out, int out_size) {
    const int*   act   = (const int*)d_in[0];
    const float* nc    = (const float*)d_in[1];
    const float* emb   = (const float*)d_in[2];
    const float* w_in  = (const float*)d_in[3];
    const float* b_in  = (const float*)d_in[4];
    const float* w_out = (const float*)d_in[5];
    const float* b_out = (const float*)d_in[6];
    float* out = (float*)d_out;
    (void)in_sizes; (void)n_in; (void)out_size;

    void *p_kv = 0, *p_q = 0, *p_ctx = 0;
    cudaGetSymbolAddress(&p_kv, g_kv);
    cudaGetSymbolAddress(&p_q, g_q);
    cudaGetSymbolAddress(&p_ctx, g_ctx);

    pack_mask_kernel<<<Bq, 256>>>(act);
    gemm_kv_h<<<dim3(8, Spad / 64), 256>>>(emb, w_in + 256 * 256, b_in + 256,
                                           (__half*)p_kv, Ssz);
    gemm_abt<<<dim3(4, 16), 256>>>(nc, w_in, b_in, (float*)p_q, Bq, 256);
    vmean1_kernel<<<400, 256>>>();
    vmean2_kernel<<<1, 256>>>();
    attn_h<<<dim3(NCH, Bq / 64, Hh), 256>>>();
    reduce_ctx_kernel<<<Bq, 256>>>();
    gemm_abt<<<dim3(4, 16), 256>>>((const float*)p_ctx, w_out, b_out, out, Bq, 256);
}

// round 6
// speedup vs baseline: 4.7035x; 1.2881x over previous
#include <cuda_runtime.h>
#include <cuda_fp16.h>
#include <cstdint>

#define Bq   1024
#define Ssz  20000
#define Spad 20032          // 64 * 313
#define Dsz  256
#define Hh   4
#define SW2  626            // mask words per batch row incl. padded word
#define NCH  9              // split-S chunks (576 CTAs ~= 2 waves at 2/SM)
#define TTOT 313            // 64-row s-tiles total

// ---------------- scratch (static device globals; no allocation) ----------------
__device__ float    g_q[Bq * Dsz];
__device__ __half   g_kv[(size_t)Spad * 512];            // [s][0:256]=k, [256:512]=v (fp16)
__device__ unsigned g_maskT[SW2 * Bq];                   // word-major: [w][b]
__device__ float    g_part[(size_t)NCH * Bq * Dsz];      // [c][b][h*64+d]
__device__ float    g_partl[NCH * Bq * Hh];
__device__ float    g_vpart[400 * Dsz];
__device__ float    g_vmean[Dsz];
__device__ float    g_ctx[Bq * Dsz];

// ---------------- helpers --------------------------------------------------------
__device__ __forceinline__ uint32_t smem_u32(const void* p) {
    uint32_t a;
    asm("{ .reg .u64 t; cvta.to.shared.u64 t, %1; cvt.u32.u64 %0, t; }" : "=r"(a) : "l"(p));
    return a;
}
__device__ __forceinline__ uint32_t h2pack(float a, float b) {
    __half2 h = __floats2half2_rn(a, b);
    return *reinterpret_cast<uint32_t*>(&h);
}
// swizzled byte offset inside a 64-col (128B-row) half tile; ch = 8-half chunk
__device__ __forceinline__ int toff(int r, int ch) {
    return r * 128 + ((ch ^ (r & 7)) << 4);
}
__device__ __forceinline__ void ldsm_x4(uint32_t& r0, uint32_t& r1, uint32_t& r2,
                                        uint32_t& r3, uint32_t addr) {
    asm volatile("ldmatrix.sync.aligned.m8n8.x4.shared.b16 {%0,%1,%2,%3}, [%4];"
                 : "=r"(r0), "=r"(r1), "=r"(r2), "=r"(r3) : "r"(addr));
}
__device__ __forceinline__ void ldsm_x4_t(uint32_t& r0, uint32_t& r1, uint32_t& r2,
                                          uint32_t& r3, uint32_t addr) {
    asm volatile("ldmatrix.sync.aligned.m8n8.x4.trans.shared.b16 {%0,%1,%2,%3}, [%4];"
                 : "=r"(r0), "=r"(r1), "=r"(r2), "=r"(r3) : "r"(addr));
}
__device__ __forceinline__ void hmma(float* d, uint32_t a0, uint32_t a1, uint32_t a2,
                                     uint32_t a3, uint32_t b0, uint32_t b1) {
    asm volatile(
        "mma.sync.aligned.m16n8k16.row.col.f32.f16.f16.f32 "
        "{%0,%1,%2,%3},{%4,%5,%6,%7},{%8,%9},{%0,%1,%2,%3};"
        : "+f"(d[0]), "+f"(d[1]), "+f"(d[2]), "+f"(d[3])
        : "r"(a0), "r"(a1), "r"(a2), "r"(a3), "r"(b0), "r"(b1));
}
__device__ __forceinline__ void cp_async16(uint32_t dst, const void* src) {
    asm volatile("cp.async.cg.shared.global [%0], [%1], 16;" :: "r"(dst), "l"(src) : "memory");
}
#define CP_COMMIT() asm volatile("cp.async.commit_group;" ::: "memory")
#define CP_WAIT1()  asm volatile("cp.async.wait_group 1;" ::: "memory")

// ---------------- mask bit-packing (transposed; padded word zeroed) --------------
__global__ void pack_mask_kernel(const int* __restrict__ act) {
    int b = blockIdx.x;
    int warp = threadIdx.x >> 5, lane = threadIdx.x & 31;
    for (int w = warp; w < SW2; w += 8) {
        int s = w * 32 + lane;
        int a = (s < Ssz) ? act[(size_t)b * Ssz + s] : 0;
        unsigned m = __ballot_sync(0xFFFFFFFFu, a > 0);
        if (lane == 0) g_maskT[w * Bq + b] = m;
    }
}

// ---------------- SIMT GEMM (two tiny 1024x256 fp32 projections) -----------------
__global__ __launch_bounds__(256) void gemm_abt(const float* __restrict__ A,
                                                const float* __restrict__ Bw,
                                                const float* __restrict__ bias,
                                                float* __restrict__ C,
                                                int M, int N) {
    __shared__ float As[16][68];
    __shared__ float Bs[16][68];
    int t  = threadIdx.x;
    int m0 = blockIdx.y * 64, n0 = blockIdx.x * 64;
    int lr = t >> 2, lc = (t & 3) * 4;
    int ty = t >> 4, tx = t & 15;
    float acc[4][4] = {};
    for (int k0 = 0; k0 < 256; k0 += 16) {
        float4 av = make_float4(0.f, 0.f, 0.f, 0.f);
        if (m0 + lr < M)
            av = *(const float4*)(A + (size_t)(m0 + lr) * 256 + k0 + lc);
        As[lc + 0][lr] = av.x; As[lc + 1][lr] = av.y;
        As[lc + 2][lr] = av.z; As[lc + 3][lr] = av.w;
        float4 bv = *(const float4*)(Bw + (size_t)(n0 + lr) * 256 + k0 + lc);
        Bs[lc + 0][lr] = bv.x; Bs[lc + 1][lr] = bv.y;
        Bs[lc + 2][lr] = bv.z; Bs[lc + 3][lr] = bv.w;
        __syncthreads();
#pragma unroll
        for (int k = 0; k < 16; k++) {
            float4 a = *(const float4*)&As[k][ty * 4];
            float4 b = *(const float4*)&Bs[k][tx * 4];
            acc[0][0] += a.x * b.x; acc[0][1] += a.x * b.y; acc[0][2] += a.x * b.z; acc[0][3] += a.x * b.w;
            acc[1][0] += a.y * b.x; acc[1][1] += a.y * b.y; acc[1][2] += a.y * b.z; acc[1][3] += a.y * b.w;
            acc[2][0] += a.z * b.x; acc[2][1] += a.z * b.y; acc[2][2] += a.z * b.z; acc[2][3] += a.z * b.w;
            acc[3][0] += a.w * b.x; acc[3][1] += a.w * b.y; acc[3][2] += a.w * b.z; acc[3][3] += a.w * b.w;
        }
        __syncthreads();
    }
    float4 bb = *(const float4*)(bias + n0 + tx * 4);
#pragma unroll
    for (int i = 0; i < 4; i++) {
        int m = m0 + ty * 4 + i;
        if (m < M) {
            float4 o = make_float4(acc[i][0] + bb.x, acc[i][1] + bb.y,
                                   acc[i][2] + bb.z, acc[i][3] + bb.w);
            *(float4*)(C + (size_t)m * N + n0 + tx * 4) = o;
        }
    }
}

// ---------------- KV projection: fp16 mma.sync + ldmatrix ------------------------
__global__ __launch_bounds__(256) void gemm_kv_h(const float* __restrict__ A,
                                                 const float* __restrict__ Bw,
                                                 const float* __restrict__ bias,
                                                 __half* __restrict__ C,
                                                 int Mreal) {
    __shared__ __align__(16) __half As[64 * 64];
    __shared__ __align__(16) __half Bs[64 * 64];
    char* ac = (char*)As; char* bc = (char*)Bs;
    const uint32_t ab = smem_u32(As), bb_ = smem_u32(Bs);
    const int t = threadIdx.x, w = t >> 5, lane = t & 31;
    const int m0 = blockIdx.y * 64, n0 = blockIdx.x * 64;
    const int mw_ = (w >> 1) * 16, nw_ = (w & 1) * 32;
    const int qr = lane >> 2, tg = lane & 3;
    const int aL4 = (lane >> 4) & 1, bL3 = (lane >> 3) & 1;
    const int ar = mw_ + (lane & 7) + (lane & 8), ar7 = ar & 7;
    const int br = nw_ + (lane & 7) + aL4 * 8, br7 = br & 7;
    float acc[4][4] = {};
    for (int k0 = 0; k0 < 256; k0 += 64) {
#pragma unroll
        for (int i = 0; i < 2; i++) {
            int idx = t + i * 256;
            int r = idx >> 3, ch = idx & 7;
            uint4 o = make_uint4(0u, 0u, 0u, 0u);
            if (m0 + r < Mreal) {
                const float* ap = A + (size_t)(m0 + r) * 256 + k0 + ch * 8;
                float4 x = *(const float4*)ap, y = *(const float4*)(ap + 4);
                o = make_uint4(h2pack(x.x, x.y), h2pack(x.z, x.w),
                               h2pack(y.x, y.y), h2pack(y.z, y.w));
            }
            *(uint4*)(ac + toff(r, ch)) = o;
            const float* bp = Bw + (size_t)(n0 + r) * 256 + k0 + ch * 8;
            float4 x = *(const float4*)bp, y = *(const float4*)(bp + 4);
            *(uint4*)(bc + toff(r, ch)) = make_uint4(h2pack(x.x, x.y), h2pack(x.z, x.w),
                                                     h2pack(y.x, y.y), h2pack(y.z, y.w));
        }
        __syncthreads();
#pragma unroll
        for (int kk = 0; kk < 64; kk += 16) {
            int c8 = kk >> 3;
            uint32_t a0, a1, a2, a3, b0, b1, b2, b3, c0, c1, c2, c3;
            ldsm_x4(a0, a1, a2, a3, ab + ar * 128 + (((c8 + aL4) ^ ar7) << 4));
            ldsm_x4(b0, b1, b2, b3, bb_ + br * 128 + (((c8 + bL3) ^ br7) << 4));
            hmma(acc[0], a0, a1, a2, a3, b0, b1);
            hmma(acc[1], a0, a1, a2, a3, b2, b3);
            ldsm_x4(c0, c1, c2, c3, bb_ + (br + 16) * 128 + (((c8 + bL3) ^ br7) << 4));
            hmma(acc[2], a0, a1, a2, a3, c0, c1);
            hmma(acc[3], a0, a1, a2, a3, c2, c3);
        }
        __syncthreads();
    }
    const int r0 = m0 + mw_ + qr, r1 = r0 + 8;
#pragma unroll
    for (int nt = 0; nt < 4; nt++) {
        int col = n0 + nw_ + nt * 8 + tg * 2;
        float bx = bias[col], by = bias[col + 1];
        *(__half2*)(C + (size_t)r0 * 512 + col) = __floats2half2_rn(acc[nt][0] + bx, acc[nt][1] + by);
        *(__half2*)(C + (size_t)r1 * 512 + col) = __floats2half2_rn(acc[nt][2] + bx, acc[nt][3] + by);
    }
}

// ---------------- v_mean (2-stage, deterministic, reads half V) ------------------
__global__ void vmean1_kernel() {
    int c = blockIdx.x, d = threadIdx.x;
    float s = 0.f;
    for (int i = 0; i < 50; i++)
        s += __half2float(g_kv[(size_t)(c * 50 + i) * 512 + 256 + d]);
    g_vpart[c * Dsz + d] = s;
}
__global__ void vmean2_kernel() {
    int d = threadIdx.x;
    float s = 0.f;
    for (int c = 0; c < 400; c++) s += g_vpart[c * Dsz + d];
    g_vmean[d] = s * (1.0f / (float)Ssz);
}

// ---------------- split-S attention: fp16 mma, register-P, cp.async pipeline ----
// CTA: 64 batch x 64 d (one head). Warp (w): rows (w>>1)*16..+15, s-half (w&1)*32.
// Per warp: QK (M16,N32,k64) -> exp in regs -> PV (M16,N64,k32). Split-k halves
// summed in smem at the end. 3-stage cp.async K/V pipeline, 1 barrier per tile.
#define A_Q   0
#define A_K   8192
#define A_V   32768
#define A_CT  57344
#define A_LS  73728
#define SM_ATT 74240

__global__ __launch_bounds__(256, 2) void attn_h2() {
    extern __shared__ __align__(16) char sm[];
    const uint32_t sb = smem_u32(sm);
    const uint32_t qb = sb + A_Q;
    float* ctxs = (float*)(sm + A_CT);
    float* lsm  = (float*)(sm + A_LS);
    const int t = threadIdx.x, w = t >> 5, lane = t & 31;
    const int c = blockIdx.x, bt = blockIdx.y, h = blockIdx.z;
    const int mw_ = (w >> 1) * 16, sh = w & 1;
    const int qr = lane >> 2, tg = lane & 3;
    const int aL4 = (lane >> 4) & 1, bL3 = (lane >> 3) & 1;
    const int ar = mw_ + (lane & 7) + (lane & 8), ar7 = ar & 7;
    const int br = sh * 32 + (lane & 7) + aL4 * 8, br7 = br & 7;
    const int vl7 = lane & 7;
    const int r0 = mw_ + qr, r1 = r0 + 8;

    { // Q tile: fp32 -> half, scaled by 1/8 (visible after first barrier)
        char* qc = sm + A_Q;
#pragma unroll
        for (int i = 0; i < 2; i++) {
            int idx = t + i * 256;
            int r = idx >> 3, ch = idx & 7;
            const float* qp = g_q + (size_t)(bt * 64 + r) * 256 + h * 64 + ch * 8;
            float4 x = *(const float4*)qp, y = *(const float4*)(qp + 4);
            *(uint4*)(qc + toff(r, ch)) =
                make_uint4(h2pack(x.x * 0.125f, x.y * 0.125f), h2pack(x.z * 0.125f, x.w * 0.125f),
                           h2pack(y.x * 0.125f, y.y * 0.125f), h2pack(y.z * 0.125f, y.w * 0.125f));
        }
    }
    const int t0 = (TTOT * c) / NCH, t1 = (TTOT * (c + 1)) / NCH;
    const int pr = t >> 3, pch = t & 7;        // prefetch map: row, chunk (2 iters)
    // prologue prefetch: tiles t0, t0+1
#pragma unroll
    for (int pf = 0; pf < 2; pf++) {
        int ts = t0 + pf;
        if (ts < t1) {
            uint32_t kd = sb + A_K + (pf) * 8192, vd = sb + A_V + (pf) * 8192;
#pragma unroll
            for (int i = 0; i < 2; i++) {
                int r = pr + i * 32;
                const __half* kp = g_kv + (size_t)(ts * 64 + r) * 512 + h * 64 + pch * 8;
                cp_async16(kd + toff(r, pch), kp);
                cp_async16(vd + toff(r, pch), kp + 256);
            }
        }
        CP_COMMIT();
    }

    float ctx[8][4] = {};
    float l0 = 0.f, l1 = 0.f;

    for (int ts = t0; ts < t1; ts++) {
        const int st = (ts - t0) % 3;
        const uint32_t kb = sb + A_K + st * 8192;
        const uint32_t vb = sb + A_V + st * 8192;
        CP_WAIT1();
        __syncthreads();
        { // prefetch ts+2 into stage (st+2)%3
            int tp = ts + 2;
            if (tp < t1) {
                int sp = (ts - t0 + 2) % 3;
                uint32_t kd = sb + A_K + sp * 8192, vd = sb + A_V + sp * 8192;
#pragma unroll
                for (int i = 0; i < 2; i++) {
                    int r = pr + i * 32;
                    const __half* kp = g_kv + (size_t)(tp * 64 + r) * 512 + h * 64 + pch * 8;
                    cp_async16(kd + toff(r, pch), kp);
                    cp_async16(vd + toff(r, pch), kp + 256);
                }
            }
            CP_COMMIT();
        }
        // mask words for this warp's rows & s-half (L2 hits; issued early)
        unsigned mwr0 = g_maskT[(size_t)(2 * ts + sh) * Bq + bt * 64 + r0];
        unsigned mwr1 = g_maskT[(size_t)(2 * ts + sh) * Bq + bt * 64 + r1];
        // ---- scores = (Q/8) @ K^T : M16 x N32 (warp s-half) x k64 ----
        float scf[4][4] = {};
#pragma unroll
        for (int kk = 0; kk < 64; kk += 16) {
            int c8 = kk >> 3;
            uint32_t a0, a1, a2, a3, b0, b1, b2, b3, c0, c1, c2, c3;
            ldsm_x4(a0, a1, a2, a3, qb + ar * 128 + (((c8 + aL4) ^ ar7) << 4));
            ldsm_x4(b0, b1, b2, b3, kb + br * 128 + (((c8 + bL3) ^ br7) << 4));
            hmma(scf[0], a0, a1, a2, a3, b0, b1);
            hmma(scf[1], a0, a1, a2, a3, b2, b3);
            ldsm_x4(c0, c1, c2, c3, kb + (br + 16) * 128 + (((c8 + bL3) ^ br7) << 4));
            hmma(scf[2], a0, a1, a2, a3, c0, c1);
            hmma(scf[3], a0, a1, a2, a3, c2, c3);
        }
        // ---- mask + exp -> A-operand fragments (registers), row sums ----
        // A-fragment order: (r0,k-lo),(r1,k-lo),(r0,k-hi),(r1,k-hi)
        uint32_t pa[2][4];
#pragma unroll
        for (int ks2 = 0; ks2 < 2; ks2++) {
#pragma unroll
            for (int q2 = 0; q2 < 2; q2++) {
                int nt = 2 * ks2 + q2;
                int bp = nt * 8 + tg * 2;
                float p00 = ((mwr0 >> bp) & 1u)       ? __expf(scf[nt][0]) : 0.f;
                float p01 = ((mwr0 >> (bp + 1)) & 1u) ? __expf(scf[nt][1]) : 0.f;
                float p10 = ((mwr1 >> bp) & 1u)       ? __expf(scf[nt][2]) : 0.f;
                float p11 = ((mwr1 >> (bp + 1)) & 1u) ? __expf(scf[nt][3]) : 0.f;
                __half2 h0 = __floats2half2_rn(p00, p01);
                __half2 h1 = __floats2half2_rn(p10, p11);
                pa[ks2][2 * q2]     = *reinterpret_cast<uint32_t*>(&h0);  // rX=r0, k chunk q2
                pa[ks2][2 * q2 + 1] = *reinterpret_cast<uint32_t*>(&h1);  // rX=r1, k chunk q2
                float2 f0 = __half22float2(h0), f1 = __half22float2(h1);
                l0 += f0.x + f0.y;
                l1 += f1.x + f1.y;
            }
        }
        // ---- ctx += P @ V : M16 x N64 x k32 (warp s-half), B via ldmatrix.trans --
#pragma unroll
        for (int ks2 = 0; ks2 < 2; ks2++) {
            int vrow = sh * 32 + ks2 * 16 + vl7 + bL3 * 8;
            uint32_t A0 = pa[ks2][0], A1 = pa[ks2][1], A2 = pa[ks2][2], A3 = pa[ks2][3];
#pragma unroll
            for (int j = 0; j < 4; j++) {
                uint32_t b0, b1, b2, b3;
                ldsm_x4_t(b0, b1, b2, b3, vb + vrow * 128 + ((((j << 1) + aL4) ^ vl7) << 4));
                hmma(ctx[2 * j],     A0, A1, A2, A3, b0, b1);
                hmma(ctx[2 * j + 1], A0, A1, A2, A3, b2, b3);
            }
        }
    }
    // ---- combine split-k halves + write partials ----
    l0 += __shfl_xor_sync(0xFFFFFFFFu, l0, 1);
    l0 += __shfl_xor_sync(0xFFFFFFFFu, l0, 2);
    l1 += __shfl_xor_sync(0xFFFFFFFFu, l1, 1);
    l1 += __shfl_xor_sync(0xFFFFFFFFu, l1, 2);
    if (sh == 1) {
#pragma unroll
        for (int nc = 0; nc < 8; nc++) {
            *(float2*)&ctxs[r0 * 64 + nc * 8 + tg * 2] = make_float2(ctx[nc][0], ctx[nc][1]);
            *(float2*)&ctxs[r1 * 64 + nc * 8 + tg * 2] = make_float2(ctx[nc][2], ctx[nc][3]);
        }
    }
    if (tg == 0) {
        lsm[sh * 64 + r0] = l0;
        lsm[sh * 64 + r1] = l1;
    }
    __syncthreads();
    if (sh == 0) {
        size_t base = ((size_t)c * Bq + bt * 64) * Dsz + (size_t)h * 64;
#pragma unroll
        for (int nc = 0; nc < 8; nc++) {
            int col = nc * 8 + tg * 2;
            float2 o0 = *(float2*)&ctxs[r0 * 64 + col];
            float2 o1 = *(float2*)&ctxs[r1 * 64 + col];
            *(float2*)(g_part + base + (size_t)r0 * Dsz + col) =
                make_float2(ctx[nc][0] + o0.x, ctx[nc][1] + o0.y);
            *(float2*)(g_part + base + (size_t)r1 * Dsz + col) =
                make_float2(ctx[nc][2] + o1.x, ctx[nc][3] + o1.y);
        }
    }
    if (t < 64)
        g_partl[((size_t)c * Bq + bt * 64 + t) * Hh + h] = lsm[t] + lsm[64 + t];
}

// ---------------- merge partials, normalize, inactive-row fallback ---------------
__global__ void reduce_ctx_kernel() {
    int b = blockIdx.x, d = threadIdx.x;
    int h = d >> 6;
    float l = 0.f, s = 0.f;
    for (int c = 0; c < NCH; c++) {
        l += g_partl[((size_t)c * Bq + b) * Hh + h];
        s += g_part[((size_t)c * Bq + b) * Dsz + d];
    }
    g_ctx[b * Dsz + d] = (l > 0.f) ? (s / l) : g_vmean[d];
}

// ---------------- launch ---------------------------------------------------------
extern "C" void kernel_launch(void* const* d_in, const int* in_sizes, int n_in,
                              void* d_out, int out_size) {
    const int*   act   = (const int*)d_in[0];
    const float* nc    = (const float*)d_in[1];
    const float* emb   = (const float*)d_in[2];
    const float* w_in  = (const float*)d_in[3];
    const float* b_in  = (const float*)d_in[4];
    const float* w_out = (const float*)d_in[5];
    const float* b_out = (const float*)d_in[6];
    float* out = (float*)d_out;
    (void)in_sizes; (void)n_in; (void)out_size;

    void *p_kv = 0, *p_q = 0, *p_ctx = 0;
    cudaGetSymbolAddress(&p_kv, g_kv);
    cudaGetSymbolAddress(&p_q, g_q);
    cudaGetSymbolAddress(&p_ctx, g_ctx);

    cudaFuncSetAttribute(attn_h2, cudaFuncAttributeMaxDynamicSharedMemorySize, SM_ATT);

    pack_mask_kernel<<<Bq, 256>>>(act);
    gemm_kv_h<<<dim3(8, Spad / 64), 256>>>(emb, w_in + 256 * 256, b_in + 256,
                                           (__half*)p_kv, Ssz);
    gemm_abt<<<dim3(4, 16), 256>>>(nc, w_in, b_in, (float*)p_q, Bq, 256);
    vmean1_kernel<<<400, 256>>>();
    vmean2_kernel<<<1, 256>>>();
    attn_h2<<<dim3(NCH, Bq / 64, Hh), 256, SM_ATT>>>();
    reduce_ctx_kernel<<<Bq, 256>>>();
    gemm_abt<<<dim3(4, 16), 256>>>((const float*)p_ctx, w_out, b_out, out, Bq, 256);
}

// round 7
// speedup vs baseline: 5.8203x; 1.2374x over previous
#include <cuda_runtime.h>
#include <cuda_fp16.h>
#include <cstdint>

#define Bq   1024
#define Ssz  20000
#define Spad 20032          // 64 * 313
#define Dsz  256
#define Hh   4
#define SW2  626            // mask words per batch row incl. padded word
#define NCH  9              // split-S chunks
#define TTOT 313            // 64-row s-tiles total

// ---------------- scratch (static device globals; no allocation) ----------------
__device__ float    g_q[Bq * Dsz];
__device__ __half   g_emb_h[(size_t)Spad * 256];         // half emb, zero-padded
__device__ __half   g_wkv_h[512 * 256];                  // half KV weight rows
__device__ __half   g_kv[(size_t)Spad * 512];            // [s][0:256]=k, [256:512]=v
__device__ unsigned g_maskT[SW2 * Bq];                   // word-major: [w][b]
__device__ float    g_part[(size_t)NCH * Bq * Dsz];      // [c][b][h*64+d]
__device__ float    g_partl[NCH * Bq * Hh];
__device__ float    g_vpart[400 * Dsz];
__device__ float    g_vmean[Dsz];
__device__ float    g_ctx[Bq * Dsz];

// ---------------- helpers --------------------------------------------------------
__device__ __forceinline__ uint32_t smem_u32(const void* p) {
    uint32_t a;
    asm("{ .reg .u64 t; cvta.to.shared.u64 t, %1; cvt.u32.u64 %0, t; }" : "=r"(a) : "l"(p));
    return a;
}
__device__ __forceinline__ uint32_t h2pack(float a, float b) {
    __half2 h = __floats2half2_rn(a, b);
    return *reinterpret_cast<uint32_t*>(&h);
}
__device__ __forceinline__ uint32_t cvt_h2(float lo, float hi) {
    uint32_t r;
    asm("cvt.rn.f16x2.f32 %0, %1, %2;" : "=r"(r) : "f"(hi), "f"(lo));
    return r;
}
__device__ __forceinline__ uint32_t ex2h2(uint32_t x) {
    uint32_t r;
    asm("ex2.approx.f16x2 %0, %1;" : "=r"(r) : "r"(x));
    return r;
}
// swizzled byte offset inside a 64-col (128B-row) half tile; ch = 8-half chunk
__device__ __forceinline__ int toff(int r, int ch) {
    return r * 128 + ((ch ^ (r & 7)) << 4);
}
__device__ __forceinline__ void ldsm_x4(uint32_t& r0, uint32_t& r1, uint32_t& r2,
                                        uint32_t& r3, uint32_t addr) {
    asm volatile("ldmatrix.sync.aligned.m8n8.x4.shared.b16 {%0,%1,%2,%3}, [%4];"
                 : "=r"(r0), "=r"(r1), "=r"(r2), "=r"(r3) : "r"(addr));
}
__device__ __forceinline__ void ldsm_x4_t(uint32_t& r0, uint32_t& r1, uint32_t& r2,
                                          uint32_t& r3, uint32_t addr) {
    asm volatile("ldmatrix.sync.aligned.m8n8.x4.trans.shared.b16 {%0,%1,%2,%3}, [%4];"
                 : "=r"(r0), "=r"(r1), "=r"(r2), "=r"(r3) : "r"(addr));
}
__device__ __forceinline__ void hmma(float* d, uint32_t a0, uint32_t a1, uint32_t a2,
                                     uint32_t a3, uint32_t b0, uint32_t b1) {
    asm volatile(
        "mma.sync.aligned.m16n8k16.row.col.f32.f16.f16.f32 "
        "{%0,%1,%2,%3},{%4,%5,%6,%7},{%8,%9},{%0,%1,%2,%3};"
        : "+f"(d[0]), "+f"(d[1]), "+f"(d[2]), "+f"(d[3])
        : "r"(a0), "r"(a1), "r"(a2), "r"(a3), "r"(b0), "r"(b1));
}
__device__ __forceinline__ void cp_async16(uint32_t dst, const void* src) {
    asm volatile("cp.async.cg.shared.global [%0], [%1], 16;" :: "r"(dst), "l"(src) : "memory");
}
#define CP_COMMIT() asm volatile("cp.async.commit_group;" ::: "memory")
#define CP_WAIT1()  asm volatile("cp.async.wait_group 1;" ::: "memory")

// ---------------- mask bit-packing (transposed; padded word zeroed) --------------
__global__ void pack_mask_kernel(const int* __restrict__ act) {
    int b = blockIdx.x;
    int warp = threadIdx.x >> 5, lane = threadIdx.x & 31;
    for (int w = warp; w < SW2; w += 8) {
        int s = w * 32 + lane;
        int a = (s < Ssz) ? act[(size_t)b * Ssz + s] : 0;
        unsigned m = __ballot_sync(0xFFFFFFFFu, a > 0);
        if (lane == 0) g_maskT[w * Bq + b] = m;
    }
}

// ---------------- fp32 -> fp16 pre-conversion (emb padded + KV weights) ----------
__global__ void conv_half(const float* __restrict__ emb, const float* __restrict__ w_in) {
    int idx = blockIdx.x * 256 + threadIdx.x;
    int r = idx >> 6, c = (idx & 63) * 4;
    if (r < Spad) {
        float4 v = make_float4(0.f, 0.f, 0.f, 0.f);
        if (r < Ssz) v = *(const float4*)(emb + (size_t)r * 256 + c);
        *(uint2*)(g_emb_h + (size_t)r * 256 + c) = make_uint2(h2pack(v.x, v.y), h2pack(v.z, v.w));
    } else {
        int rw = r - Spad;
        float4 v = *(const float4*)(w_in + (size_t)(256 + rw) * 256 + c);
        *(uint2*)(g_wkv_h + rw * 256 + c) = make_uint2(h2pack(v.x, v.y), h2pack(v.z, v.w));
    }
}

// ---------------- SIMT GEMM (two tiny 1024x256 fp32 projections) -----------------
__global__ __launch_bounds__(256) void gemm_abt(const float* __restrict__ A,
                                                const float* __restrict__ Bw,
                                                const float* __restrict__ bias,
                                                float* __restrict__ C,
                                                int M, int N) {
    __shared__ float As[16][68];
    __shared__ float Bs[16][68];
    int t  = threadIdx.x;
    int m0 = blockIdx.y * 64, n0 = blockIdx.x * 64;
    int lr = t >> 2, lc = (t & 3) * 4;
    int ty = t >> 4, tx = t & 15;
    float acc[4][4] = {};
    for (int k0 = 0; k0 < 256; k0 += 16) {
        float4 av = make_float4(0.f, 0.f, 0.f, 0.f);
        if (m0 + lr < M)
            av = *(const float4*)(A + (size_t)(m0 + lr) * 256 + k0 + lc);
        As[lc + 0][lr] = av.x; As[lc + 1][lr] = av.y;
        As[lc + 2][lr] = av.z; As[lc + 3][lr] = av.w;
        float4 bv = *(const float4*)(Bw + (size_t)(n0 + lr) * 256 + k0 + lc);
        Bs[lc + 0][lr] = bv.x; Bs[lc + 1][lr] = bv.y;
        Bs[lc + 2][lr] = bv.z; Bs[lc + 3][lr] = bv.w;
        __syncthreads();
#pragma unroll
        for (int k = 0; k < 16; k++) {
            float4 a = *(const float4*)&As[k][ty * 4];
            float4 b = *(const float4*)&Bs[k][tx * 4];
            acc[0][0] += a.x * b.x; acc[0][1] += a.x * b.y; acc[0][2] += a.x * b.z; acc[0][3] += a.x * b.w;
            acc[1][0] += a.y * b.x; acc[1][1] += a.y * b.y; acc[1][2] += a.y * b.z; acc[1][3] += a.y * b.w;
            acc[2][0] += a.z * b.x; acc[2][1] += a.z * b.y; acc[2][2] += a.z * b.z; acc[2][3] += a.z * b.w;
            acc[3][0] += a.w * b.x; acc[3][1] += a.w * b.y; acc[3][2] += a.w * b.z; acc[3][3] += a.w * b.w;
        }
        __syncthreads();
    }
    float4 bb = *(const float4*)(bias + n0 + tx * 4);
#pragma unroll
    for (int i = 0; i < 4; i++) {
        int m = m0 + ty * 4 + i;
        if (m < M) {
            float4 o = make_float4(acc[i][0] + bb.x, acc[i][1] + bb.y,
                                   acc[i][2] + bb.z, acc[i][3] + bb.w);
            *(float4*)(C + (size_t)m * N + n0 + tx * 4) = o;
        }
    }
}

// ---------------- KV projection: fp16 mma + cp.async 3-stage pipeline ------------
// C[Spad x 512] (half) = emb_h[s][256] @ wkv_h[n][256]^T + bias[n]
#define KV_STG 16384
__global__ __launch_bounds__(256) void gemm_kv_p(const float* __restrict__ bias,
                                                 __half* __restrict__ C) {
    extern __shared__ __align__(16) char sm[];
    const uint32_t sb = smem_u32(sm);
    const int t = threadIdx.x, w = t >> 5, lane = t & 31;
    const int m0 = blockIdx.y * 64, n0 = blockIdx.x * 64;
    const int mw_ = (w >> 1) * 16, nw_ = (w & 1) * 32;
    const int qr = lane >> 2, tg = lane & 3;
    const int aL4 = (lane >> 4) & 1, bL3 = (lane >> 3) & 1;
    const int ar = mw_ + (lane & 7) + (lane & 8), ar7 = ar & 7;
    const int br = nw_ + (lane & 7) + aL4 * 8, br7 = br & 7;
    const int pr = t >> 3, pch = t & 7;
    // prologue: prefetch k-steps 0,1
#pragma unroll
    for (int pf = 0; pf < 2; pf++) {
        uint32_t base = sb + pf * KV_STG;
#pragma unroll
        for (int i = 0; i < 2; i++) {
            int r = pr + i * 32;
            cp_async16(base + toff(r, pch),
                       g_emb_h + (size_t)(m0 + r) * 256 + pf * 64 + pch * 8);
            cp_async16(base + 8192 + toff(r, pch),
                       g_wkv_h + (n0 + r) * 256 + pf * 64 + pch * 8);
        }
        CP_COMMIT();
    }
    float acc[4][4] = {};
    for (int k0 = 0; k0 < 4; k0++) {
        const int st = k0 % 3;
        const uint32_t ab = sb + st * KV_STG, bb_ = ab + 8192;
        CP_WAIT1();
        __syncthreads();
        {
            int kp = k0 + 2;
            if (kp < 4) {
                uint32_t base = sb + (kp % 3) * KV_STG;
#pragma unroll
                for (int i = 0; i < 2; i++) {
                    int r = pr + i * 32;
                    cp_async16(base + toff(r, pch),
                               g_emb_h + (size_t)(m0 + r) * 256 + kp * 64 + pch * 8);
                    cp_async16(base + 8192 + toff(r, pch),
                               g_wkv_h + (n0 + r) * 256 + kp * 64 + pch * 8);
                }
            }
            CP_COMMIT();
        }
#pragma unroll
        for (int kk = 0; kk < 64; kk += 16) {
            int c8 = kk >> 3;
            uint32_t a0, a1, a2, a3, b0, b1, b2, b3, c0, c1, c2, c3;
            ldsm_x4(a0, a1, a2, a3, ab + ar * 128 + (((c8 + aL4) ^ ar7) << 4));
            ldsm_x4(b0, b1, b2, b3, bb_ + br * 128 + (((c8 + bL3) ^ br7) << 4));
            hmma(acc[0], a0, a1, a2, a3, b0, b1);
            hmma(acc[1], a0, a1, a2, a3, b2, b3);
            ldsm_x4(c0, c1, c2, c3, bb_ + (br + 16) * 128 + (((c8 + bL3) ^ br7) << 4));
            hmma(acc[2], a0, a1, a2, a3, c0, c1);
            hmma(acc[3], a0, a1, a2, a3, c2, c3);
        }
    }
    const int r0 = m0 + mw_ + qr, r1 = r0 + 8;
#pragma unroll
    for (int nt = 0; nt < 4; nt++) {
        int col = n0 + nw_ + nt * 8 + tg * 2;
        float bx = bias[col], by = bias[col + 1];
        *(__half2*)(C + (size_t)r0 * 512 + col) = __floats2half2_rn(acc[nt][0] + bx, acc[nt][1] + by);
        *(__half2*)(C + (size_t)r1 * 512 + col) = __floats2half2_rn(acc[nt][2] + bx, acc[nt][3] + by);
    }
}

// ---------------- v_mean (2-stage, deterministic, reads half V) ------------------
__global__ void vmean1_kernel() {
    int c = blockIdx.x, d = threadIdx.x;
    float s = 0.f;
    for (int i = 0; i < 50; i++)
        s += __half2float(g_kv[(size_t)(c * 50 + i) * 512 + 256 + d]);
    g_vpart[c * Dsz + d] = s;
}
__global__ void vmean2_kernel() {
    int d = threadIdx.x;
    float s = 0.f;
    for (int c = 0; c < 400; c++) s += g_vpart[c * Dsz + d];
    g_vmean[d] = s * (1.0f / (float)Ssz);
}

// ---------------- split-S attention: fp16 mma, register-P, cp.async pipeline ----
// ex2.f16x2 exp path (log2e folded into Q), l-sum via HMMA-with-ones.
#define A_Q   0
#define A_K   8192
#define A_V   32768
#define A_CT  57344
#define A_LS  73728
#define SM_ATT 74240
#define ONES2 0x3C003C00u

__global__ __launch_bounds__(256, 2) void attn_h2() {
    extern __shared__ __align__(16) char sm[];
    const uint32_t sb = smem_u32(sm);
    const uint32_t qb = sb + A_Q;
    float* ctxs = (float*)(sm + A_CT);
    float* lsm  = (float*)(sm + A_LS);
    const int t = threadIdx.x, w = t >> 5, lane = t & 31;
    const int c = blockIdx.x, bt = blockIdx.y, h = blockIdx.z;
    const int mw_ = (w >> 1) * 16, sh = w & 1;
    const int qr = lane >> 2, tg = lane & 3;
    const int aL4 = (lane >> 4) & 1, bL3 = (lane >> 3) & 1;
    const int ar = mw_ + (lane & 7) + (lane & 8), ar7 = ar & 7;
    const int br = sh * 32 + (lane & 7) + aL4 * 8, br7 = br & 7;
    const int vl7 = lane & 7;
    const int r0 = mw_ + qr, r1 = r0 + 8;

    { // Q tile: fp32 -> half, scale = (1/8)*log2(e)  (so exp(s) = 2^score)
        const float QS = 0.125f * 1.44269504f;
        char* qc = sm + A_Q;
#pragma unroll
        for (int i = 0; i < 2; i++) {
            int idx = t + i * 256;
            int r = idx >> 3, ch = idx & 7;
            const float* qp = g_q + (size_t)(bt * 64 + r) * 256 + h * 64 + ch * 8;
            float4 x = *(const float4*)qp, y = *(const float4*)(qp + 4);
            *(uint4*)(qc + toff(r, ch)) =
                make_uint4(h2pack(x.x * QS, x.y * QS), h2pack(x.z * QS, x.w * QS),
                           h2pack(y.x * QS, y.y * QS), h2pack(y.z * QS, y.w * QS));
        }
    }
    const int t0 = (TTOT * c) / NCH, t1 = (TTOT * (c + 1)) / NCH;
    const int pr = t >> 3, pch = t & 7;
    // prologue prefetch: tiles t0, t0+1
#pragma unroll
    for (int pf = 0; pf < 2; pf++) {
        int ts = t0 + pf;
        if (ts < t1) {
            uint32_t kd = sb + A_K + pf * 8192, vd = sb + A_V + pf * 8192;
#pragma unroll
            for (int i = 0; i < 2; i++) {
                int r = pr + i * 32;
                const __half* kp = g_kv + (size_t)(ts * 64 + r) * 512 + h * 64 + pch * 8;
                cp_async16(kd + toff(r, pch), kp);
                cp_async16(vd + toff(r, pch), kp + 256);
            }
        }
        CP_COMMIT();
    }
    __syncthreads();          // Q tile visible
    // hoist loop-invariant Q A-fragments
    uint32_t qa[4][4];
#pragma unroll
    for (int kk4 = 0; kk4 < 4; kk4++)
        ldsm_x4(qa[kk4][0], qa[kk4][1], qa[kk4][2], qa[kk4][3],
                qb + ar * 128 + ((((kk4 * 2) + aL4) ^ ar7) << 4));

    float ctx[8][4] = {};
    float lacc[4] = {};

    for (int ts = t0; ts < t1; ts++) {
        const int st = (ts - t0) % 3;
        const uint32_t kb = sb + A_K + st * 8192;
        const uint32_t vb = sb + A_V + st * 8192;
        CP_WAIT1();
        __syncthreads();
        { // prefetch ts+2
            int tp = ts + 2;
            if (tp < t1) {
                int sp = (ts - t0 + 2) % 3;
                uint32_t kd = sb + A_K + sp * 8192, vd = sb + A_V + sp * 8192;
#pragma unroll
                for (int i = 0; i < 2; i++) {
                    int r = pr + i * 32;
                    const __half* kp = g_kv + (size_t)(tp * 64 + r) * 512 + h * 64 + pch * 8;
                    cp_async16(kd + toff(r, pch), kp);
                    cp_async16(vd + toff(r, pch), kp + 256);
                }
            }
            CP_COMMIT();
        }
        unsigned mwr0 = g_maskT[(size_t)(2 * ts + sh) * Bq + bt * 64 + r0];
        unsigned mwr1 = g_maskT[(size_t)(2 * ts + sh) * Bq + bt * 64 + r1];
        // ---- scores(log2) = Q' @ K^T : M16 x N32 x k64 ----
        float scf[4][4] = {};
#pragma unroll
        for (int kk = 0; kk < 64; kk += 16) {
            int c8 = kk >> 3, kq = kk >> 4;
            uint32_t b0, b1, b2, b3, c0, c1, c2, c3;
            ldsm_x4(b0, b1, b2, b3, kb + br * 128 + (((c8 + bL3) ^ br7) << 4));
            hmma(scf[0], qa[kq][0], qa[kq][1], qa[kq][2], qa[kq][3], b0, b1);
            hmma(scf[1], qa[kq][0], qa[kq][1], qa[kq][2], qa[kq][3], b2, b3);
            ldsm_x4(c0, c1, c2, c3, kb + (br + 16) * 128 + (((c8 + bL3) ^ br7) << 4));
            hmma(scf[2], qa[kq][0], qa[kq][1], qa[kq][2], qa[kq][3], c0, c1);
            hmma(scf[3], qa[kq][0], qa[kq][1], qa[kq][2], qa[kq][3], c2, c3);
        }
        // ---- p = 2^score via ex2.f16x2, mask by AND; l-sum via HMMA-ones ----
        uint32_t pa[2][4];
#pragma unroll
        for (int ks2 = 0; ks2 < 2; ks2++) {
#pragma unroll
            for (int q2 = 0; q2 < 2; q2++) {
                int nt = 2 * ks2 + q2;
                int bp = nt * 8 + tg * 2;
                uint32_t am0 = (((mwr0 >> bp) & 1u) ? 0x0000FFFFu : 0u) |
                               (((mwr0 >> (bp + 1)) & 1u) ? 0xFFFF0000u : 0u);
                uint32_t am1 = (((mwr1 >> bp) & 1u) ? 0x0000FFFFu : 0u) |
                               (((mwr1 >> (bp + 1)) & 1u) ? 0xFFFF0000u : 0u);
                pa[ks2][2 * q2]     = ex2h2(cvt_h2(scf[nt][0], scf[nt][1])) & am0;
                pa[ks2][2 * q2 + 1] = ex2h2(cvt_h2(scf[nt][2], scf[nt][3])) & am1;
            }
            hmma(lacc, pa[ks2][0], pa[ks2][1], pa[ks2][2], pa[ks2][3], ONES2, ONES2);
        }
        // ---- ctx += P @ V : M16 x N64 x k32, B via ldmatrix.trans ----
#pragma unroll
        for (int ks2 = 0; ks2 < 2; ks2++) {
            int vrow = sh * 32 + ks2 * 16 + vl7 + bL3 * 8;
            uint32_t A0 = pa[ks2][0], A1 = pa[ks2][1], A2 = pa[ks2][2], A3 = pa[ks2][3];
#pragma unroll
            for (int j = 0; j < 4; j++) {
                uint32_t b0, b1, b2, b3;
                ldsm_x4_t(b0, b1, b2, b3, vb + vrow * 128 + ((((j << 1) + aL4) ^ vl7) << 4));
                hmma(ctx[2 * j],     A0, A1, A2, A3, b0, b1);
                hmma(ctx[2 * j + 1], A0, A1, A2, A3, b2, b3);
            }
        }
    }
    // ---- combine split-k halves + write partials ----
    if (sh == 1) {
#pragma unroll
        for (int nc = 0; nc < 8; nc++) {
            *(float2*)&ctxs[r0 * 64 + nc * 8 + tg * 2] = make_float2(ctx[nc][0], ctx[nc][1]);
            *(float2*)&ctxs[r1 * 64 + nc * 8 + tg * 2] = make_float2(ctx[nc][2], ctx[nc][3]);
        }
    }
    if (tg == 0) {            // lacc[0]/lacc[2] are full half-row sums (ones-B)
        lsm[sh * 64 + r0] = lacc[0];
        lsm[sh * 64 + r1] = lacc[2];
    }
    __syncthreads();
    if (sh == 0) {
        size_t base = ((size_t)c * Bq + bt * 64) * Dsz + (size_t)h * 64;
#pragma unroll
        for (int nc = 0; nc < 8; nc++) {
            int col = nc * 8 + tg * 2;
            float2 o0 = *(float2*)&ctxs[r0 * 64 + col];
            float2 o1 = *(float2*)&ctxs[r1 * 64 + col];
            *(float2*)(g_part + base + (size_t)r0 * Dsz + col) =
                make_float2(ctx[nc][0] + o0.x, ctx[nc][1] + o0.y);
            *(float2*)(g_part + base + (size_t)r1 * Dsz + col) =
                make_float2(ctx[nc][2] + o1.x, ctx[nc][3] + o1.y);
        }
    }
    if (t < 64)
        g_partl[((size_t)c * Bq + bt * 64 + t) * Hh + h] = lsm[t] + lsm[64 + t];
}

// ---------------- merge partials, normalize, inactive-row fallback ---------------
__global__ void reduce_ctx_kernel() {
    int b = blockIdx.x, d = threadIdx.x;
    int h = d >> 6;
    float l = 0.f, s = 0.f;
    for (int c = 0; c < NCH; c++) {
        l += g_partl[((size_t)c * Bq + b) * Hh + h];
        s += g_part[((size_t)c * Bq + b) * Dsz + d];
    }
    g_ctx[b * Dsz + d] = (l > 0.f) ? (s / l) : g_vmean[d];
}

// ---------------- launch ---------------------------------------------------------
extern "C" void kernel_launch(void* const* d_in, const int* in_sizes, int n_in,
                              void* d_out, int out_size) {
    const int*   act   = (const int*)d_in[0];
    const float* nc    = (const float*)d_in[1];
    const float* emb   = (const float*)d_in[2];
    const float* w_in  = (const float*)d_in[3];
    const float* b_in  = (const float*)d_in[4];
    const float* w_out = (const float*)d_in[5];
    const float* b_out = (const float*)d_in[6];
    float* out = (float*)d_out;
    (void)in_sizes; (void)n_in; (void)out_size;

    void *p_kv = 0, *p_q = 0, *p_ctx = 0;
    cudaGetSymbolAddress(&p_kv, g_kv);
    cudaGetSymbolAddress(&p_q, g_q);
    cudaGetSymbolAddress(&p_ctx, g_ctx);

    cudaFuncSetAttribute(attn_h2, cudaFuncAttributeMaxDynamicSharedMemorySize, SM_ATT);
    cudaFuncSetAttribute(gemm_kv_p, cudaFuncAttributeMaxDynamicSharedMemorySize, 3 * KV_STG);

    pack_mask_kernel<<<Bq, 256>>>(act);
    conv_half<<<(Spad + 512) * 64 / 256, 256>>>(emb, w_in);
    gemm_kv_p<<<dim3(8, Spad / 64), 256, 3 * KV_STG>>>(b_in + 256, (__half*)p_kv);
    gemm_abt<<<dim3(4, 16), 256>>>(nc, w_in, b_in, (float*)p_q, Bq, 256);
    vmean1_kernel<<<400, 256>>>();
    vmean2_kernel<<<1, 256>>>();
    attn_h2<<<dim3(NCH, Bq / 64, Hh), 256, SM_ATT>>>();
    reduce_ctx_kernel<<<Bq, 256>>>();
    gemm_abt<<<dim3(4, 16), 256>>>((const float*)p_ctx, w_out, b_out, out, Bq, 256);
}

// round 8
// speedup vs baseline: 6.7685x; 1.1629x over previous
#include <cuda_runtime.h>
#include <cuda_fp16.h>
#include <cstdint>

#define Bq   1024
#define Ssz  20000
#define Spad 20032          // 64 * 313
#define Dsz  256
#define Hh   4
#define SW2  626            // mask words per batch row incl. padded word
#define NCH  9              // split-S chunks
#define TTOT 313            // 64-row s-tiles total

// ---------------- scratch (static device globals; no allocation) ----------------
__device__ float    g_q[Bq * Dsz];
__device__ __half   g_emb_h[(size_t)Spad * 256];         // half emb, zero-padded
__device__ __half   g_wkv_h[512 * 256];                  // half KV weight rows
__device__ __half   g_nc_h[Bq * 256];                    // half neural_context
__device__ __half   g_wq_h[256 * 256];                   // half Q weight rows
__device__ __half   g_wo_h[256 * 256];                   // half out-proj weights
__device__ __half   g_ctx_h[Bq * Dsz];                   // half ctx (out-proj A)
__device__ __half   g_kv[(size_t)Spad * 512];            // [s][0:256]=k, [256:512]=v
__device__ unsigned g_maskT[SW2 * Bq];                   // word-major: [w][b]
__device__ float    g_part[(size_t)NCH * Bq * Dsz];      // [c][b][h*64+d]
__device__ float    g_partl[NCH * Bq * Hh];
__device__ float    g_vpart[400 * Dsz];
__device__ float    g_vmean[Dsz];

// ---------------- helpers --------------------------------------------------------
__device__ __forceinline__ uint32_t smem_u32(const void* p) {
    uint32_t a;
    asm("{ .reg .u64 t; cvta.to.shared.u64 t, %1; cvt.u32.u64 %0, t; }" : "=r"(a) : "l"(p));
    return a;
}
__device__ __forceinline__ uint32_t h2pack(float a, float b) {
    __half2 h = __floats2half2_rn(a, b);
    return *reinterpret_cast<uint32_t*>(&h);
}
__device__ __forceinline__ uint32_t cvt_h2(float lo, float hi) {
    uint32_t r;
    asm("cvt.rn.f16x2.f32 %0, %1, %2;" : "=r"(r) : "f"(hi), "f"(lo));
    return r;
}
__device__ __forceinline__ uint32_t ex2h2(uint32_t x) {
    uint32_t r;
    asm("ex2.approx.f16x2 %0, %1;" : "=r"(r) : "r"(x));
    return r;
}
// swizzled byte offset inside a 64-col (128B-row) half tile; ch = 8-half chunk
__device__ __forceinline__ int toff(int r, int ch) {
    return r * 128 + ((ch ^ (r & 7)) << 4);
}
__device__ __forceinline__ void ldsm_x4(uint32_t& r0, uint32_t& r1, uint32_t& r2,
                                        uint32_t& r3, uint32_t addr) {
    asm volatile("ldmatrix.sync.aligned.m8n8.x4.shared.b16 {%0,%1,%2,%3}, [%4];"
                 : "=r"(r0), "=r"(r1), "=r"(r2), "=r"(r3) : "r"(addr));
}
__device__ __forceinline__ void ldsm_x4_t(uint32_t& r0, uint32_t& r1, uint32_t& r2,
                                          uint32_t& r3, uint32_t addr) {
    asm volatile("ldmatrix.sync.aligned.m8n8.x4.trans.shared.b16 {%0,%1,%2,%3}, [%4];"
                 : "=r"(r0), "=r"(r1), "=r"(r2), "=r"(r3) : "r"(addr));
}
__device__ __forceinline__ void hmma(float* d, uint32_t a0, uint32_t a1, uint32_t a2,
                                     uint32_t a3, uint32_t b0, uint32_t b1) {
    asm volatile(
        "mma.sync.aligned.m16n8k16.row.col.f32.f16.f16.f32 "
        "{%0,%1,%2,%3},{%4,%5,%6,%7},{%8,%9},{%0,%1,%2,%3};"
        : "+f"(d[0]), "+f"(d[1]), "+f"(d[2]), "+f"(d[3])
        : "r"(a0), "r"(a1), "r"(a2), "r"(a3), "r"(b0), "r"(b1));
}
__device__ __forceinline__ void cp_async16(uint32_t dst, const void* src) {
    asm volatile("cp.async.cg.shared.global [%0], [%1], 16;" :: "r"(dst), "l"(src) : "memory");
}
#define CP_COMMIT() asm volatile("cp.async.commit_group;" ::: "memory")
#define CP_WAIT1()  asm volatile("cp.async.wait_group 1;" ::: "memory")

// ---------------- mask bit-packing (transposed; padded word zeroed) --------------
__global__ void pack_mask_kernel(const int* __restrict__ act) {
    int b = blockIdx.x;
    int warp = threadIdx.x >> 5, lane = threadIdx.x & 31;
    for (int w = warp; w < SW2; w += 8) {
        int s = w * 32 + lane;
        int a = (s < Ssz) ? act[(size_t)b * Ssz + s] : 0;
        unsigned m = __ballot_sync(0xFFFFFFFFu, a > 0);
        if (lane == 0) g_maskT[w * Bq + b] = m;
    }
}

// ---------------- fp32 -> fp16 pre-conversion ------------------------------------
// rows: [0,Spad)=emb, [Spad,+512)=W_kv, [+1024)=nc, [+256)=W_q, [+256)=W_out
#define CROWS (Spad + 512 + Bq + 256 + 256)
__global__ void conv_half(const float* __restrict__ emb, const float* __restrict__ w_in,
                          const float* __restrict__ nc, const float* __restrict__ w_out) {
    int idx = blockIdx.x * 256 + threadIdx.x;
    int r = idx >> 6, c = (idx & 63) * 4;
    if (r < Spad) {
        float4 v = make_float4(0.f, 0.f, 0.f, 0.f);
        if (r < Ssz) v = *(const float4*)(emb + (size_t)r * 256 + c);
        *(uint2*)(g_emb_h + (size_t)r * 256 + c) = make_uint2(h2pack(v.x, v.y), h2pack(v.z, v.w));
    } else if (r < Spad + 512) {
        int rw = r - Spad;
        float4 v = *(const float4*)(w_in + (size_t)(256 + rw) * 256 + c);
        *(uint2*)(g_wkv_h + rw * 256 + c) = make_uint2(h2pack(v.x, v.y), h2pack(v.z, v.w));
    } else if (r < Spad + 512 + Bq) {
        int rn = r - Spad - 512;
        float4 v = *(const float4*)(nc + (size_t)rn * 256 + c);
        *(uint2*)(g_nc_h + rn * 256 + c) = make_uint2(h2pack(v.x, v.y), h2pack(v.z, v.w));
    } else if (r < Spad + 512 + Bq + 256) {
        int rw = r - Spad - 512 - Bq;
        float4 v = *(const float4*)(w_in + (size_t)rw * 256 + c);
        *(uint2*)(g_wq_h + rw * 256 + c) = make_uint2(h2pack(v.x, v.y), h2pack(v.z, v.w));
    } else if (r < CROWS) {
        int rw = r - Spad - 512 - Bq - 256;
        float4 v = *(const float4*)(w_out + (size_t)rw * 256 + c);
        *(uint2*)(g_wo_h + rw * 256 + c) = make_uint2(h2pack(v.x, v.y), h2pack(v.z, v.w));
    }
}

// ---------------- fp16 GEMM, fp32 out: C[1024 x 256] = A_h @ B_h^T + bias --------
#define GH_STG 16384
__global__ __launch_bounds__(256) void gemm_h(const __half* __restrict__ Ah,
                                              const __half* __restrict__ Bh,
                                              const float* __restrict__ bias,
                                              float* __restrict__ C) {
    extern __shared__ __align__(16) char sm[];
    const uint32_t sb = smem_u32(sm);
    const int t = threadIdx.x, w = t >> 5, lane = t & 31;
    const int m0 = blockIdx.y * 64, n0 = blockIdx.x * 64;
    const int mw_ = (w >> 1) * 16, nw_ = (w & 1) * 32;
    const int qr = lane >> 2, tg = lane & 3;
    const int aL4 = (lane >> 4) & 1, bL3 = (lane >> 3) & 1;
    const int ar = mw_ + (lane & 7) + (lane & 8), ar7 = ar & 7;
    const int br = nw_ + (lane & 7) + aL4 * 8, br7 = br & 7;
    const int pr = t >> 3, pch = t & 7;
#pragma unroll
    for (int pf = 0; pf < 2; pf++) {
        uint32_t base = sb + pf * GH_STG;
#pragma unroll
        for (int i = 0; i < 2; i++) {
            int r = pr + i * 32;
            cp_async16(base + toff(r, pch), Ah + (size_t)(m0 + r) * 256 + pf * 64 + pch * 8);
            cp_async16(base + 8192 + toff(r, pch), Bh + (n0 + r) * 256 + pf * 64 + pch * 8);
        }
        CP_COMMIT();
    }
    float acc[4][4] = {};
    for (int k0 = 0; k0 < 4; k0++) {
        const uint32_t ab = sb + (k0 % 3) * GH_STG, bb_ = ab + 8192;
        CP_WAIT1();
        __syncthreads();
        {
            int kp = k0 + 2;
            if (kp < 4) {
                uint32_t base = sb + (kp % 3) * GH_STG;
#pragma unroll
                for (int i = 0; i < 2; i++) {
                    int r = pr + i * 32;
                    cp_async16(base + toff(r, pch), Ah + (size_t)(m0 + r) * 256 + kp * 64 + pch * 8);
                    cp_async16(base + 8192 + toff(r, pch), Bh + (n0 + r) * 256 + kp * 64 + pch * 8);
                }
            }
            CP_COMMIT();
        }
#pragma unroll
        for (int kk = 0; kk < 64; kk += 16) {
            int c8 = kk >> 3;
            uint32_t a0, a1, a2, a3, b0, b1, b2, b3, c0, c1, c2, c3;
            ldsm_x4(a0, a1, a2, a3, ab + ar * 128 + (((c8 + aL4) ^ ar7) << 4));
            ldsm_x4(b0, b1, b2, b3, bb_ + br * 128 + (((c8 + bL3) ^ br7) << 4));
            hmma(acc[0], a0, a1, a2, a3, b0, b1);
            hmma(acc[1], a0, a1, a2, a3, b2, b3);
            ldsm_x4(c0, c1, c2, c3, bb_ + (br + 16) * 128 + (((c8 + bL3) ^ br7) << 4));
            hmma(acc[2], a0, a1, a2, a3, c0, c1);
            hmma(acc[3], a0, a1, a2, a3, c2, c3);
        }
    }
    const int r0 = m0 + mw_ + qr, r1 = r0 + 8;
#pragma unroll
    for (int nt = 0; nt < 4; nt++) {
        int col = n0 + nw_ + nt * 8 + tg * 2;
        float bx = bias[col], by = bias[col + 1];
        *(float2*)(C + (size_t)r0 * 256 + col) = make_float2(acc[nt][0] + bx, acc[nt][1] + by);
        *(float2*)(C + (size_t)r1 * 256 + col) = make_float2(acc[nt][2] + bx, acc[nt][3] + by);
    }
}

// ---------------- KV projection: fp16 mma + cp.async 3-stage pipeline ------------
#define KV_STG 16384
__global__ __launch_bounds__(256) void gemm_kv_p(const float* __restrict__ bias,
                                                 __half* __restrict__ C) {
    extern __shared__ __align__(16) char sm[];
    const uint32_t sb = smem_u32(sm);
    const int t = threadIdx.x, w = t >> 5, lane = t & 31;
    const int m0 = blockIdx.y * 64, n0 = blockIdx.x * 64;
    const int mw_ = (w >> 1) * 16, nw_ = (w & 1) * 32;
    const int qr = lane >> 2, tg = lane & 3;
    const int aL4 = (lane >> 4) & 1, bL3 = (lane >> 3) & 1;
    const int ar = mw_ + (lane & 7) + (lane & 8), ar7 = ar & 7;
    const int br = nw_ + (lane & 7) + aL4 * 8, br7 = br & 7;
    const int pr = t >> 3, pch = t & 7;
#pragma unroll
    for (int pf = 0; pf < 2; pf++) {
        uint32_t base = sb + pf * KV_STG;
#pragma unroll
        for (int i = 0; i < 2; i++) {
            int r = pr + i * 32;
            cp_async16(base + toff(r, pch),
                       g_emb_h + (size_t)(m0 + r) * 256 + pf * 64 + pch * 8);
            cp_async16(base + 8192 + toff(r, pch),
                       g_wkv_h + (n0 + r) * 256 + pf * 64 + pch * 8);
        }
        CP_COMMIT();
    }
    float acc[4][4] = {};
    for (int k0 = 0; k0 < 4; k0++) {
        const uint32_t ab = sb + (k0 % 3) * KV_STG, bb_ = ab + 8192;
        CP_WAIT1();
        __syncthreads();
        {
            int kp = k0 + 2;
            if (kp < 4) {
                uint32_t base = sb + (kp % 3) * KV_STG;
#pragma unroll
                for (int i = 0; i < 2; i++) {
                    int r = pr + i * 32;
                    cp_async16(base + toff(r, pch),
                               g_emb_h + (size_t)(m0 + r) * 256 + kp * 64 + pch * 8);
                    cp_async16(base + 8192 + toff(r, pch),
                               g_wkv_h + (n0 + r) * 256 + kp * 64 + pch * 8);
                }
            }
            CP_COMMIT();
        }
#pragma unroll
        for (int kk = 0; kk < 64; kk += 16) {
            int c8 = kk >> 3;
            uint32_t a0, a1, a2, a3, b0, b1, b2, b3, c0, c1, c2, c3;
            ldsm_x4(a0, a1, a2, a3, ab + ar * 128 + (((c8 + aL4) ^ ar7) << 4));
            ldsm_x4(b0, b1, b2, b3, bb_ + br * 128 + (((c8 + bL3) ^ br7) << 4));
            hmma(acc[0], a0, a1, a2, a3, b0, b1);
            hmma(acc[1], a0, a1, a2, a3, b2, b3);
            ldsm_x4(c0, c1, c2, c3, bb_ + (br + 16) * 128 + (((c8 + bL3) ^ br7) << 4));
            hmma(acc[2], a0, a1, a2, a3, c0, c1);
            hmma(acc[3], a0, a1, a2, a3, c2, c3);
        }
    }
    const int r0 = m0 + mw_ + qr, r1 = r0 + 8;
#pragma unroll
    for (int nt = 0; nt < 4; nt++) {
        int col = n0 + nw_ + nt * 8 + tg * 2;
        float bx = bias[col], by = bias[col + 1];
        *(__half2*)(C + (size_t)r0 * 512 + col) = __floats2half2_rn(acc[nt][0] + bx, acc[nt][1] + by);
        *(__half2*)(C + (size_t)r1 * 512 + col) = __floats2half2_rn(acc[nt][2] + bx, acc[nt][3] + by);
    }
}

// ---------------- v_mean (2-stage, deterministic, reads half V) ------------------
__global__ void vmean1_kernel() {
    int c = blockIdx.x, d = threadIdx.x;
    float s = 0.f;
    for (int i = 0; i < 50; i++)
        s += __half2float(g_kv[(size_t)(c * 50 + i) * 512 + 256 + d]);
    g_vpart[c * Dsz + d] = s;
}
__global__ void vmean2_kernel() {
    int d = threadIdx.x;
    float s = 0.f;
    for (int c = 0; c < 400; c++) s += g_vpart[c * Dsz + d];
    g_vmean[d] = s * (1.0f / (float)Ssz);
}

// ---------------- split-S attention: fp16 mma, register-P, cp.async pipeline ----
#define A_Q   0
#define A_K   8192
#define A_V   32768
#define A_CT  57344
#define A_LS  73728
#define SM_ATT 74240
#define ONES2 0x3C003C00u

__global__ __launch_bounds__(256, 2) void attn_h2() {
    extern __shared__ __align__(16) char sm[];
    const uint32_t sb = smem_u32(sm);
    const uint32_t qb = sb + A_Q;
    float* ctxs = (float*)(sm + A_CT);
    float* lsm  = (float*)(sm + A_LS);
    const int t = threadIdx.x, w = t >> 5, lane = t & 31;
    const int c = blockIdx.x, bt = blockIdx.y, h = blockIdx.z;
    const int mw_ = (w >> 1) * 16, sh = w & 1;
    const int qr = lane >> 2, tg = lane & 3;
    const int aL4 = (lane >> 4) & 1, bL3 = (lane >> 3) & 1;
    const int ar = mw_ + (lane & 7) + (lane & 8), ar7 = ar & 7;
    const int br = sh * 32 + (lane & 7) + aL4 * 8, br7 = br & 7;
    const int vl7 = lane & 7;
    const int r0 = mw_ + qr, r1 = r0 + 8;

    { // Q tile: fp32 -> half, scale = (1/8)*log2(e)
        const float QS = 0.125f * 1.44269504f;
        char* qc = sm + A_Q;
#pragma unroll
        for (int i = 0; i < 2; i++) {
            int idx = t + i * 256;
            int r = idx >> 3, ch = idx & 7;
            const float* qp = g_q + (size_t)(bt * 64 + r) * 256 + h * 64 + ch * 8;
            float4 x = *(const float4*)qp, y = *(const float4*)(qp + 4);
            *(uint4*)(qc + toff(r, ch)) =
                make_uint4(h2pack(x.x * QS, x.y * QS), h2pack(x.z * QS, x.w * QS),
                           h2pack(y.x * QS, y.y * QS), h2pack(y.z * QS, y.w * QS));
        }
    }
    const int t0 = (TTOT * c) / NCH, t1 = (TTOT * (c + 1)) / NCH;
    const int pr = t >> 3, pch = t & 7;
#pragma unroll
    for (int pf = 0; pf < 2; pf++) {
        int ts = t0 + pf;
        if (ts < t1) {
            uint32_t kd = sb + A_K + pf * 8192, vd = sb + A_V + pf * 8192;
#pragma unroll
            for (int i = 0; i < 2; i++) {
                int r = pr + i * 32;
                const __half* kp = g_kv + (size_t)(ts * 64 + r) * 512 + h * 64 + pch * 8;
                cp_async16(kd + toff(r, pch), kp);
                cp_async16(vd + toff(r, pch), kp + 256);
            }
        }
        CP_COMMIT();
    }
    __syncthreads();          // Q tile visible
    uint32_t qa[4][4];
#pragma unroll
    for (int kk4 = 0; kk4 < 4; kk4++)
        ldsm_x4(qa[kk4][0], qa[kk4][1], qa[kk4][2], qa[kk4][3],
                qb + ar * 128 + ((((kk4 * 2) + aL4) ^ ar7) << 4));

    float ctx[8][4] = {};
    float lacc[4] = {};

    for (int ts = t0; ts < t1; ts++) {
        const int st = (ts - t0) % 3;
        const uint32_t kb = sb + A_K + st * 8192;
        const uint32_t vb = sb + A_V + st * 8192;
        CP_WAIT1();
        __syncthreads();
        { // prefetch ts+2
            int tp = ts + 2;
            if (tp < t1) {
                int sp = (ts - t0 + 2) % 3;
                uint32_t kd = sb + A_K + sp * 8192, vd = sb + A_V + sp * 8192;
#pragma unroll
                for (int i = 0; i < 2; i++) {
                    int r = pr + i * 32;
                    const __half* kp = g_kv + (size_t)(tp * 64 + r) * 512 + h * 64 + pch * 8;
                    cp_async16(kd + toff(r, pch), kp);
                    cp_async16(vd + toff(r, pch), kp + 256);
                }
            }
            CP_COMMIT();
        }
        unsigned mwr0 = g_maskT[(size_t)(2 * ts + sh) * Bq + bt * 64 + r0];
        unsigned mwr1 = g_maskT[(size_t)(2 * ts + sh) * Bq + bt * 64 + r1];
        float scf[4][4] = {};
#pragma unroll
        for (int kk = 0; kk < 64; kk += 16) {
            int c8 = kk >> 3, kq = kk >> 4;
            uint32_t b0, b1, b2, b3, c0, c1, c2, c3;
            ldsm_x4(b0, b1, b2, b3, kb + br * 128 + (((c8 + bL3) ^ br7) << 4));
            hmma(scf[0], qa[kq][0], qa[kq][1], qa[kq][2], qa[kq][3], b0, b1);
            hmma(scf[1], qa[kq][0], qa[kq][1], qa[kq][2], qa[kq][3], b2, b3);
            ldsm_x4(c0, c1, c2, c3, kb + (br + 16) * 128 + (((c8 + bL3) ^ br7) << 4));
            hmma(scf[2], qa[kq][0], qa[kq][1], qa[kq][2], qa[kq][3], c0, c1);
            hmma(scf[3], qa[kq][0], qa[kq][1], qa[kq][2], qa[kq][3], c2, c3);
        }
        uint32_t pa[2][4];
#pragma unroll
        for (int ks2 = 0; ks2 < 2; ks2++) {
#pragma unroll
            for (int q2 = 0; q2 < 2; q2++) {
                int nt = 2 * ks2 + q2;
                int bp = nt * 8 + tg * 2;
                uint32_t am0 = (((mwr0 >> bp) & 1u) ? 0x0000FFFFu : 0u) |
                               (((mwr0 >> (bp + 1)) & 1u) ? 0xFFFF0000u : 0u);
                uint32_t am1 = (((mwr1 >> bp) & 1u) ? 0x0000FFFFu : 0u) |
                               (((mwr1 >> (bp + 1)) & 1u) ? 0xFFFF0000u : 0u);
                pa[ks2][2 * q2]     = ex2h2(cvt_h2(scf[nt][0], scf[nt][1])) & am0;
                pa[ks2][2 * q2 + 1] = ex2h2(cvt_h2(scf[nt][2], scf[nt][3])) & am1;
            }
            hmma(lacc, pa[ks2][0], pa[ks2][1], pa[ks2][2], pa[ks2][3], ONES2, ONES2);
        }
#pragma unroll
        for (int ks2 = 0; ks2 < 2; ks2++) {
            int vrow = sh * 32 + ks2 * 16 + vl7 + bL3 * 8;
            uint32_t A0 = pa[ks2][0], A1 = pa[ks2][1], A2 = pa[ks2][2], A3 = pa[ks2][3];
#pragma unroll
            for (int j = 0; j < 4; j++) {
                uint32_t b0, b1, b2, b3;
                ldsm_x4_t(b0, b1, b2, b3, vb + vrow * 128 + ((((j << 1) + aL4) ^ vl7) << 4));
                hmma(ctx[2 * j],     A0, A1, A2, A3, b0, b1);
                hmma(ctx[2 * j + 1], A0, A1, A2, A3, b2, b3);
            }
        }
    }
    if (sh == 1) {
#pragma unroll
        for (int nc = 0; nc < 8; nc++) {
            *(float2*)&ctxs[r0 * 64 + nc * 8 + tg * 2] = make_float2(ctx[nc][0], ctx[nc][1]);
            *(float2*)&ctxs[r1 * 64 + nc * 8 + tg * 2] = make_float2(ctx[nc][2], ctx[nc][3]);
        }
    }
    if (tg == 0) {
        lsm[sh * 64 + r0] = lacc[0];
        lsm[sh * 64 + r1] = lacc[2];
    }
    __syncthreads();
    if (sh == 0) {
        size_t base = ((size_t)c * Bq + bt * 64) * Dsz + (size_t)h * 64;
#pragma unroll
        for (int nc = 0; nc < 8; nc++) {
            int col = nc * 8 + tg * 2;
            float2 o0 = *(float2*)&ctxs[r0 * 64 + col];
            float2 o1 = *(float2*)&ctxs[r1 * 64 + col];
            *(float2*)(g_part + base + (size_t)r0 * Dsz + col) =
                make_float2(ctx[nc][0] + o0.x, ctx[nc][1] + o0.y);
            *(float2*)(g_part + base + (size_t)r1 * Dsz + col) =
                make_float2(ctx[nc][2] + o1.x, ctx[nc][3] + o1.y);
        }
    }
    if (t < 64)
        g_partl[((size_t)c * Bq + bt * 64 + t) * Hh + h] = lsm[t] + lsm[64 + t];
}

// ---------------- merge partials, normalize (half ctx out) -----------------------
__global__ void reduce_ctx_kernel() {
    int b = blockIdx.x, d = threadIdx.x;
    int h = d >> 6;
    float l = 0.f, s = 0.f;
    for (int c = 0; c < NCH; c++) {
        l += g_partl[((size_t)c * Bq + b) * Hh + h];
        s += g_part[((size_t)c * Bq + b) * Dsz + d];
    }
    float v = (l > 0.f) ? (s / l) : g_vmean[d];
    g_ctx_h[b * Dsz + d] = __float2half_rn(v);
}

// ---------------- launch ---------------------------------------------------------
extern "C" void kernel_launch(void* const* d_in, const int* in_sizes, int n_in,
                              void* d_out, int out_size) {
    const int*   act   = (const int*)d_in[0];
    const float* nc    = (const float*)d_in[1];
    const float* emb   = (const float*)d_in[2];
    const float* w_in  = (const float*)d_in[3];
    const float* b_in  = (const float*)d_in[4];
    const float* w_out = (const float*)d_in[5];
    const float* b_out = (const float*)d_in[6];
    float* out = (float*)d_out;
    (void)in_sizes; (void)n_in; (void)out_size;

    void *p_kv = 0, *p_q = 0;
    void *p_nc = 0, *p_wq = 0, *p_wo = 0, *p_ctx = 0;
    cudaGetSymbolAddress(&p_kv, g_kv);
    cudaGetSymbolAddress(&p_q, g_q);
    cudaGetSymbolAddress(&p_nc, g_nc_h);
    cudaGetSymbolAddress(&p_wq, g_wq_h);
    cudaGetSymbolAddress(&p_wo, g_wo_h);
    cudaGetSymbolAddress(&p_ctx, g_ctx_h);

    cudaFuncSetAttribute(attn_h2, cudaFuncAttributeMaxDynamicSharedMemorySize, SM_ATT);
    cudaFuncSetAttribute(gemm_kv_p, cudaFuncAttributeMaxDynamicSharedMemorySize, 3 * KV_STG);
    cudaFuncSetAttribute(gemm_h, cudaFuncAttributeMaxDynamicSharedMemorySize, 3 * GH_STG);

    pack_mask_kernel<<<Bq, 256>>>(act);
    conv_half<<<CROWS / 4, 256>>>(emb, w_in, nc, w_out);
    gemm_kv_p<<<dim3(8, Spad / 64), 256, 3 * KV_STG>>>(b_in + 256, (__half*)p_kv);
    gemm_h<<<dim3(4, 16), 256, 3 * GH_STG>>>((const __half*)p_nc, (const __half*)p_wq,
                                             b_in, (float*)p_q);
    vmean1_kernel<<<400, 256>>>();
    vmean2_kernel<<<1, 256>>>();
    attn_h2<<<dim3(NCH, Bq / 64, Hh), 256, SM_ATT>>>();
    reduce_ctx_kernel<<<Bq, 256>>>();
    gemm_h<<<dim3(4, 16), 256, 3 * GH_STG>>>((const __half*)p_ctx, (const __half*)p_wo,
                                             b_out, out);
}